// round 2
// baseline (speedup 1.0000x reference)
#include <cuda_runtime.h>
#include <math.h>

#define BATCH 1024
#define L 32
#define D 128
#define NNODE 50000
#define ROWS (BATCH * L)           // 32768
#define RD   (ROWS * D)            // 4194304

// ---------------- flat scratch: one static device global, offsets passed as args ----
// Layout (float offsets):
//   HIN=0, HOUT=RD, A=2RD(+2RD), GI=4RD(+3RD), GH=7RD(+3RD),
//   INTRA=10RD, FINAL=11RD, FW2=12RD, HS=13RD(+BATCH*D)
#define OFF_HIN   0
#define OFF_HOUT  (RD)
#define OFF_A     (2 * RD)
#define OFF_GI    (4 * RD)
#define OFF_GH    (7 * RD)
#define OFF_INTRA (10 * RD)
#define OFF_FINAL (11 * RD)
#define OFF_FW2   (12 * RD)
#define OFF_HS    (13 * RD)
#define SCRATCH_TOTAL (13 * RD + BATCH * D)

__device__ float g_scratch[SCRATCH_TOTAL];

// ---------------- f32x2 helpers (FFMA2 path) ----------------
__device__ __forceinline__ unsigned long long pk2(float x, float y) {
    unsigned long long r;
    asm("mov.b64 %0, {%1,%2};" : "=l"(r) : "f"(x), "f"(y));
    return r;
}
__device__ __forceinline__ void fma2(unsigned long long& c, unsigned long long a, unsigned long long b) {
    asm("fma.rn.f32x2 %0, %1, %2, %0;" : "+l"(c) : "l"(a), "l"(b));
}
__device__ __forceinline__ float2 unpk(unsigned long long c) {
    float2 v;
    asm("mov.b64 {%0,%1}, %2;" : "=f"(v.x), "=f"(v.y) : "l"(c));
    return v;
}

__device__ __forceinline__ float sigf(float x) { return 1.0f / (1.0f + expf(-x)); }

// ---------------- generic NN GEMM: C[M,N] = A[M,K] @ W[K,N] (+bias) ----------------
// Tiles: 64x64x16, 256 threads, 4x4 microtile, f32x2 inner loop.
// A: if GATHER, row m = emb[idx[m]] (A_ext = emb); else A_ext if non-null, else scratch+a_off.
// C: always scratch + c_off. All M,N,K here are exact tile multiples -> no guards.
template <bool GATHER>
__global__ void __launch_bounds__(256) gemm_nn(
    const float* __restrict__ A_ext, long a_off, const int* __restrict__ idx,
    const float* __restrict__ Bm, const float* __restrict__ bias,
    long c_off, int M, int N, int K)
{
    const float* A = A_ext ? A_ext : (g_scratch + a_off);
    float* C = g_scratch + c_off;

    __shared__ __align__(16) float As[16 * 68];
    __shared__ __align__(16) float Bs[16 * 68];
    const int t  = threadIdx.x;
    const int bm = blockIdx.y * 64, bn = blockIdx.x * 64;
    const int tm = (t >> 4) << 2, tn = (t & 15) << 2;
    const int lar = t >> 2, lak = (t & 3) << 2;     // A tile: row 0..63, k 0,4,8,12
    const int lbk = t >> 4, lbn = (t & 15) << 2;    // B tile: k 0..15, n 0..60

    const long arow = bm + lar;
    const float* Ap = GATHER ? (A + (long)idx[arow] * K) : (A + arow * (long)K);
    const float* Bp = Bm + (long)lbk * N + bn + lbn;

    unsigned long long c[4][2] = {};

    for (int k0 = 0; k0 < K; k0 += 16) {
        float4 av = *(const float4*)(Ap + k0 + lak);
        float4 bv = *(const float4*)(Bp + (long)k0 * N);
        __syncthreads();
        As[(lak + 0) * 68 + lar] = av.x;
        As[(lak + 1) * 68 + lar] = av.y;
        As[(lak + 2) * 68 + lar] = av.z;
        As[(lak + 3) * 68 + lar] = av.w;
        *(float4*)&Bs[lbk * 68 + lbn] = bv;
        __syncthreads();
#pragma unroll
        for (int k = 0; k < 16; k++) {
            float4 a = *(const float4*)&As[k * 68 + tm];
            unsigned long long b01 = *(const unsigned long long*)&Bs[k * 68 + tn];
            unsigned long long b23 = *(const unsigned long long*)&Bs[k * 68 + tn + 2];
            unsigned long long ad;
            ad = pk2(a.x, a.x); fma2(c[0][0], ad, b01); fma2(c[0][1], ad, b23);
            ad = pk2(a.y, a.y); fma2(c[1][0], ad, b01); fma2(c[1][1], ad, b23);
            ad = pk2(a.z, a.z); fma2(c[2][0], ad, b01); fma2(c[2][1], ad, b23);
            ad = pk2(a.w, a.w); fma2(c[3][0], ad, b01); fma2(c[3][1], ad, b23);
        }
    }

    float bb0 = 0.f, bb1 = 0.f, bb2 = 0.f, bb3 = 0.f;
    if (bias) {
        bb0 = bias[bn + tn + 0]; bb1 = bias[bn + tn + 1];
        bb2 = bias[bn + tn + 2]; bb3 = bias[bn + tn + 3];
    }
#pragma unroll
    for (int i = 0; i < 4; i++) {
        int row = bm + tm + i;
        float2 v0 = unpk(c[i][0]), v1 = unpk(c[i][1]);
        float* Cp = C + (long)row * N + bn + tn;
        Cp[0] = v0.x + bb0; Cp[1] = v0.y + bb1;
        Cp[2] = v1.x + bb2; Cp[3] = v1.y + bb3;
    }
}

// ---------------- NT GEMM: C[M,N] = A[M,K] @ B[N,K]^T (scores = hs @ emb^T) --------
__global__ void __launch_bounds__(256) gemm_nt(
    long a_off, const float* __restrict__ Bm,
    float* __restrict__ C, int M, int N, int K)
{
    const float* A = g_scratch + a_off;

    __shared__ __align__(16) float As[16 * 68];
    __shared__ __align__(16) float Bs[16 * 68];
    const int t  = threadIdx.x;
    const int bm = blockIdx.y * 64, bn = blockIdx.x * 64;
    const int tm = (t >> 4) << 2, tn = (t & 15) << 2;
    const int lr = t >> 2, lk = (t & 3) << 2;

    const float* Ap = A + (long)(bm + lr) * K;
    const long nrow = bn + lr;
    const bool bvalid = (nrow < N);
    const float* Bp = bvalid ? (Bm + nrow * (long)K) : Bm;

    unsigned long long c[4][2] = {};

    for (int k0 = 0; k0 < K; k0 += 16) {
        float4 av = *(const float4*)(Ap + k0 + lk);
        float4 bv = make_float4(0.f, 0.f, 0.f, 0.f);
        if (bvalid) bv = *(const float4*)(Bp + k0 + lk);
        __syncthreads();
        As[(lk + 0) * 68 + lr] = av.x;
        As[(lk + 1) * 68 + lr] = av.y;
        As[(lk + 2) * 68 + lr] = av.z;
        As[(lk + 3) * 68 + lr] = av.w;
        Bs[(lk + 0) * 68 + lr] = bv.x;
        Bs[(lk + 1) * 68 + lr] = bv.y;
        Bs[(lk + 2) * 68 + lr] = bv.z;
        Bs[(lk + 3) * 68 + lr] = bv.w;
        __syncthreads();
#pragma unroll
        for (int k = 0; k < 16; k++) {
            float4 a = *(const float4*)&As[k * 68 + tm];
            unsigned long long b01 = *(const unsigned long long*)&Bs[k * 68 + tn];
            unsigned long long b23 = *(const unsigned long long*)&Bs[k * 68 + tn + 2];
            unsigned long long ad;
            ad = pk2(a.x, a.x); fma2(c[0][0], ad, b01); fma2(c[0][1], ad, b23);
            ad = pk2(a.y, a.y); fma2(c[1][0], ad, b01); fma2(c[1][1], ad, b23);
            ad = pk2(a.z, a.z); fma2(c[2][0], ad, b01); fma2(c[2][1], ad, b23);
            ad = pk2(a.w, a.w); fma2(c[3][0], ad, b01); fma2(c[3][1], ad, b23);
        }
    }
#pragma unroll
    for (int i = 0; i < 4; i++) {
        int row = bm + tm + i;             // M = 1024, exact -> no row guard
        int n0  = bn + tn;
        float2 v0 = unpk(c[i][0]), v1 = unpk(c[i][1]);
        float* Cp = C + (long)row * N + n0;
        if (n0 + 0 < N) Cp[0] = v0.x;
        if (n0 + 1 < N) Cp[1] = v0.y;
        if (n0 + 2 < N) Cp[2] = v1.x;
        if (n0 + 3 < N) Cp[3] = v1.y;
    }
}

// ---------------- adjacency: a_in = A_in[b] @ hWin[b], a_out likewise; writes concat -
__global__ void __launch_bounds__(128) adj_kernel(
    const float* __restrict__ Ain, const float* __restrict__ Aout,
    long hin_off, long hout_off, long out_off)
{
    const float* hin  = g_scratch + hin_off;
    const float* hout = g_scratch + hout_off;
    float* out = g_scratch + out_off;

    const int b = blockIdx.x;
    const int d = threadIdx.x;
    __shared__ float sAi[L * L], sAo[L * L];
    __shared__ float shi[L * D], sho[L * D];
    const float* Aib = Ain + (long)b * L * L;
    const float* Aob = Aout + (long)b * L * L;
    const float* hib = hin + (long)b * L * D;
    const float* hob = hout + (long)b * L * D;
    for (int i = d; i < L * L; i += 128) { sAi[i] = Aib[i]; sAo[i] = Aob[i]; }
    for (int i = d; i < L * D; i += 128) { shi[i] = hib[i]; sho[i] = hob[i]; }
    __syncthreads();
    for (int l = 0; l < L; l++) {
        float si = 0.f, so = 0.f;
#pragma unroll 8
        for (int m = 0; m < L; m++) {
            si += sAi[l * L + m] * shi[m * D + d];
            so += sAo[l * L + m] * sho[m * D + d];
        }
        long o = ((long)b * L + l) * (2 * D);
        out[o + d]     = si;
        out[o + D + d] = so;
    }
}

// ---------------- GRU gates (torch r,z,n order) ----------------
// hprev source: items!=null -> gather emb[items]; else hprev_ext (real input ptr).
__global__ void __launch_bounds__(256) gru_kernel(
    long gi_off, long gh_off,
    const float* __restrict__ hprev_ext, const int* __restrict__ items,
    const float* __restrict__ emb, long out_off)
{
    const float* gi = g_scratch + gi_off;
    const float* gh = g_scratch + gh_off;
    float* out = g_scratch + out_off;

    long i = (long)blockIdx.x * blockDim.x + threadIdx.x;
    if (i >= (long)ROWS * D) return;
    int row = (int)(i >> 7), d = (int)(i & 127);
    long gb = (long)row * (3 * D);
    float ir = gi[gb + d], iz = gi[gb + D + d], in_ = gi[gb + 2 * D + d];
    float hr = gh[gb + d], hz = gh[gb + D + d], hn  = gh[gb + 2 * D + d];
    float hp = items ? emb[(long)items[row] * D + d] : hprev_ext[i];
    float r = sigf(ir + hr);
    float z = sigf(iz + hz);
    float n = tanhf(in_ + r * hn);
    out[i] = (1.0f - z) * n + z * hp;
}

// ---------------- attention readout: v_n, gates, alpha, s_g, h_s ----------------
__global__ void __launch_bounds__(128) readout_kernel(
    long fin_off, long fW2_off,
    const int* __restrict__ seq_len,
    const float* __restrict__ W1, const float* __restrict__ b1,
    const float* __restrict__ wq, const float* __restrict__ bq,
    const float* __restrict__ W3, const float* __restrict__ b3,
    long hs_off)
{
    const float* fin = g_scratch + fin_off;
    const float* fW2 = g_scratch + fW2_off;
    float* hs = g_scratch + hs_off;

    const int b = blockIdx.x;
    const int d = threadIdx.x;
    __shared__ float svn[D];
    __shared__ float sg_sh[D];
    __shared__ float gmat[L * D];
    __shared__ float alpha[L];

    const int sl = seq_len[b];
    const float* finb = fin + (long)b * L * D;
    svn[d] = finb[(long)(sl - 1) * D + d];
    __syncthreads();

    // q1 = v_n @ W1 + b1
    float q = b1[d];
    for (int k = 0; k < D; k++) q += svn[k] * W1[k * D + d];

    // gates = sigmoid(q1 + final@W2 + b2) (fW2 already has b2)
    const float* fW2b = fW2 + (long)b * L * D;
    for (int l = 0; l < L; l++)
        gmat[l * D + d] = sigf(q + fW2b[l * D + d]);
    __syncthreads();

    // alpha[l] = gates[l] . wq + bq
    int w = d >> 5, lane = d & 31;
    for (int l = w; l < L; l += 4) {
        float p = 0.f;
        for (int kk = lane; kk < D; kk += 32) p += gmat[l * D + kk] * wq[kk];
#pragma unroll
        for (int off = 16; off; off >>= 1) p += __shfl_xor_sync(0xFFFFFFFFu, p, off);
        if (lane == 0) alpha[l] = p + bq[0];
    }
    __syncthreads();

    // s_g = sum over valid l of alpha[l] * final[l]
    float sg = 0.f;
    for (int l = 0; l < sl; l++) sg += alpha[l] * finb[(long)l * D + d];
    sg_sh[d] = sg;
    __syncthreads();

    // h_s = concat(v_n, s_g) @ W3 + b3
    float o = b3[d];
    for (int k = 0; k < D; k++) {
        o += svn[k]   * W3[k * D + d];
        o += sg_sh[k] * W3[(D + k) * D + d];
    }
    hs[(long)b * D + d] = o;
}

// ---------------- launcher: pure kernel launches, no runtime API ----------------
extern "C" void kernel_launch(void* const* d_in, const int* in_sizes, int n_in,
                              void* d_out, int out_size)
{
    const int*   items  = (const int*)d_in[0];
    const float* A_in   = (const float*)d_in[1];
    const float* A_out  = (const float*)d_in[2];
    const float* inter  = (const float*)d_in[3];
    const int*   seqlen = (const int*)d_in[4];
    const float* emb    = (const float*)d_in[5];
    const float* W_in   = (const float*)d_in[6];
    const float* b_in   = (const float*)d_in[7];
    const float* W_out  = (const float*)d_in[8];
    const float* b_out  = (const float*)d_in[9];
    const float* W_a    = (const float*)d_in[10];
    const float* U_h    = (const float*)d_in[11];
    const float* b_gru  = (const float*)d_in[12];
    const float* Wi     = (const float*)d_in[13];
    const float* bi     = (const float*)d_in[14];
    const float* Wh     = (const float*)d_in[15];
    const float* bh     = (const float*)d_in[16];
    const float* W1     = (const float*)d_in[17];
    const float* b1     = (const float*)d_in[18];
    const float* W2     = (const float*)d_in[19];
    const float* b2     = (const float*)d_in[20];
    const float* wq     = (const float*)d_in[21];
    const float* bq     = (const float*)d_in[22];
    const float* W3     = (const float*)d_in[23];
    const float* b3     = (const float*)d_in[24];
    float* scores = (float*)d_out;

    const int MT = ROWS / 64;  // 512 M-tiles

    // 1-2: hWin/hWout = emb[items] @ W_{in,out} + b
    gemm_nn<true><<<dim3(D / 64, MT), 256>>>(emb, 0, items, W_in,  b_in,  OFF_HIN,  ROWS, D, D);
    gemm_nn<true><<<dim3(D / 64, MT), 256>>>(emb, 0, items, W_out, b_out, OFF_HOUT, ROWS, D, D);
    // 3: a = concat(A_in@hWin, A_out@hWout)
    adj_kernel<<<BATCH, 128>>>(A_in, A_out, OFF_HIN, OFF_HOUT, OFF_A);
    // 4-5: GRU1 gate inputs
    gemm_nn<false><<<dim3(384 / 64, MT), 256>>>(nullptr, OFF_A, nullptr, W_a, b_gru,   OFF_GI, ROWS, 384, 2 * D);
    gemm_nn<true><<<dim3(384 / 64, MT), 256>>>(emb, 0, items, U_h, nullptr, OFF_GH, ROWS, 384, D);
    // 6: intra
    gru_kernel<<<(ROWS * D) / 256, 256>>>(OFF_GI, OFF_GH, nullptr, items, emb, OFF_INTRA);
    // 7-8: GRU2 gate inputs (reuse gi/gh)
    gemm_nn<false><<<dim3(384 / 64, MT), 256>>>(nullptr, OFF_INTRA, nullptr, Wi, bi, OFF_GI, ROWS, 384, D);
    gemm_nn<false><<<dim3(384 / 64, MT), 256>>>(inter, 0, nullptr, Wh, bh, OFF_GH, ROWS, 384, D);
    // 9: final
    gru_kernel<<<(ROWS * D) / 256, 256>>>(OFF_GI, OFF_GH, inter, nullptr, nullptr, OFF_FINAL);
    // 10: fW2 = final @ W2 + b2
    gemm_nn<false><<<dim3(D / 64, MT), 256>>>(nullptr, OFF_FINAL, nullptr, W2, b2, OFF_FW2, ROWS, D, D);
    // 11: attention readout -> h_s
    readout_kernel<<<BATCH, 128>>>(OFF_FINAL, OFF_FW2, seqlen, W1, b1, wq, bq, W3, b3, OFF_HS);
    // 12: scores = h_s @ emb^T
    gemm_nt<<<dim3((NNODE + 63) / 64, BATCH / 64), 256>>>(OFF_HS, emb, scores, BATCH, NNODE, D);
}

// round 3
// speedup vs baseline: 1.1068x; 1.1068x over previous
#include <cuda_runtime.h>
#include <math.h>

#define BATCH 1024
#define L 32
#define D 128
#define NNODE 50000
#define ROWS (BATCH * L)           // 32768
#define RD   (ROWS * D)            // 4194304

// ---------------- flat scratch ----------------
#define OFF_HIN   0
#define OFF_HOUT  (RD)
#define OFF_A     (2 * RD)
#define OFF_GI    (4 * RD)
#define OFF_GH    (7 * RD)
#define OFF_INTRA (10 * RD)
#define OFF_FINAL (11 * RD)
#define OFF_FW2   (12 * RD)
#define OFF_HS    (13 * RD)
#define SCRATCH_TOTAL (13 * RD + BATCH * D)

__device__ float g_scratch[SCRATCH_TOTAL];

// ---------------- f32x2 helpers (FFMA2 path) ----------------
__device__ __forceinline__ unsigned long long pk2(float x, float y) {
    unsigned long long r;
    asm("mov.b64 %0, {%1,%2};" : "=l"(r) : "f"(x), "f"(y));
    return r;
}
__device__ __forceinline__ void fma2(unsigned long long& c, unsigned long long a, unsigned long long b) {
    asm("fma.rn.f32x2 %0, %1, %2, %0;" : "+l"(c) : "l"(a), "l"(b));
}
__device__ __forceinline__ float2 unpk(unsigned long long c) {
    float2 v;
    asm("mov.b64 {%0,%1}, %2;" : "=f"(v.x), "=f"(v.y) : "l"(c));
    return v;
}
__device__ __forceinline__ float sigf(float x) { return 1.0f / (1.0f + expf(-x)); }

#define TS 132   // smem tile row stride (floats); 16B-aligned rows

// 8-row FMA block for one k
#define FMA_ROWS(a0, a1, b0, b1)                                                            \
    {                                                                                       \
        unsigned long long ad;                                                              \
        ad = pk2(a0.x, a0.x); fma2(c[0][0], ad, b0.x); fma2(c[0][1], ad, b0.y);             \
                              fma2(c[0][2], ad, b1.x); fma2(c[0][3], ad, b1.y);             \
        ad = pk2(a0.y, a0.y); fma2(c[1][0], ad, b0.x); fma2(c[1][1], ad, b0.y);             \
                              fma2(c[1][2], ad, b1.x); fma2(c[1][3], ad, b1.y);             \
        ad = pk2(a0.z, a0.z); fma2(c[2][0], ad, b0.x); fma2(c[2][1], ad, b0.y);             \
                              fma2(c[2][2], ad, b1.x); fma2(c[2][3], ad, b1.y);             \
        ad = pk2(a0.w, a0.w); fma2(c[3][0], ad, b0.x); fma2(c[3][1], ad, b0.y);             \
                              fma2(c[3][2], ad, b1.x); fma2(c[3][3], ad, b1.y);             \
        ad = pk2(a1.x, a1.x); fma2(c[4][0], ad, b0.x); fma2(c[4][1], ad, b0.y);             \
                              fma2(c[4][2], ad, b1.x); fma2(c[4][3], ad, b1.y);             \
        ad = pk2(a1.y, a1.y); fma2(c[5][0], ad, b0.x); fma2(c[5][1], ad, b0.y);             \
                              fma2(c[5][2], ad, b1.x); fma2(c[5][3], ad, b1.y);             \
        ad = pk2(a1.z, a1.z); fma2(c[6][0], ad, b0.x); fma2(c[6][1], ad, b0.y);             \
                              fma2(c[6][2], ad, b1.x); fma2(c[6][3], ad, b1.y);             \
        ad = pk2(a1.w, a1.w); fma2(c[7][0], ad, b0.x); fma2(c[7][1], ad, b0.y);             \
                              fma2(c[7][2], ad, b1.x); fma2(c[7][3], ad, b1.y);             \
    }

// ---------------- NN GEMM: C[M,N] = A[M,K] @ W[K,N] (+bias) ----------------
// 128x128x16 block tile, 256 threads, 8x8 microtile, f32x2 accumulators.
// Warp covers 32(M)x64(N); within warp 4 M-groups x 8 N-groups -> A-LDS broadcast.
// All M,N,K exact tile multiples here -> no guards.
template <bool GATHER>
__global__ void __launch_bounds__(256, 2) gemm_nn(
    const float* __restrict__ A_ext, long a_off, const int* __restrict__ idx,
    const float* __restrict__ Bm, const float* __restrict__ bias,
    long c_off, int M, int N, int K)
{
    const float* A = A_ext ? A_ext : (g_scratch + a_off);
    float* C = g_scratch + c_off;

    __shared__ __align__(16) float As[16 * TS];
    __shared__ __align__(16) float Bs[16 * TS];

    const int t = threadIdx.x;
    const int bm = blockIdx.y * 128, bn = blockIdx.x * 128;

    const int warp = t >> 5, lane = t & 31;
    const int tm = (warp >> 1) * 32 + (lane >> 3) * 8;
    const int tn = (warp & 1) * 64 + (lane & 7) * 8;

    // fill indices
    const int ar = t >> 1, ak = (t & 1) << 3;     // A: row 0..127, k 0 or 8
    const int kb = t >> 4, nb = (t & 15) << 3;    // B: k 0..15,  n 0..120

    const long arow = bm + ar;
    const float* Ap = GATHER ? (A + (long)idx[arow] * K) : (A + arow * (long)K);

    unsigned long long c[8][4] = {};

    float4 pa0 = *(const float4*)(Ap + ak);
    float4 pa1 = *(const float4*)(Ap + ak + 4);
    const float* bp0 = Bm + (long)kb * N + bn + nb;
    float4 pb0 = *(const float4*)(bp0);
    float4 pb1 = *(const float4*)(bp0 + 4);

    for (int k0 = 0; k0 < K; k0 += 16) {
        __syncthreads();
        As[(ak + 0) * TS + ar] = pa0.x;
        As[(ak + 1) * TS + ar] = pa0.y;
        As[(ak + 2) * TS + ar] = pa0.z;
        As[(ak + 3) * TS + ar] = pa0.w;
        As[(ak + 4) * TS + ar] = pa1.x;
        As[(ak + 5) * TS + ar] = pa1.y;
        As[(ak + 6) * TS + ar] = pa1.z;
        As[(ak + 7) * TS + ar] = pa1.w;
        *(float4*)&Bs[kb * TS + nb]     = pb0;
        *(float4*)&Bs[kb * TS + nb + 4] = pb1;
        __syncthreads();
        if (k0 + 16 < K) {
            pa0 = *(const float4*)(Ap + k0 + 16 + ak);
            pa1 = *(const float4*)(Ap + k0 + 16 + ak + 4);
            const float* bp = Bm + (long)(k0 + 16 + kb) * N + bn + nb;
            pb0 = *(const float4*)(bp);
            pb1 = *(const float4*)(bp + 4);
        }
#pragma unroll
        for (int k = 0; k < 16; k++) {
            const float* as = &As[k * TS + tm];
            float4 a0 = *(const float4*)as;
            float4 a1 = *(const float4*)(as + 4);
            const float* bs = &Bs[k * TS + tn];
            ulonglong2 b0 = *(const ulonglong2*)bs;
            ulonglong2 b1 = *(const ulonglong2*)(bs + 4);
            FMA_ROWS(a0, a1, b0, b1);
        }
    }

    float4 bb0 = make_float4(0.f, 0.f, 0.f, 0.f), bb1 = bb0;
    if (bias) {
        bb0 = *(const float4*)(bias + bn + tn);
        bb1 = *(const float4*)(bias + bn + tn + 4);
    }
#pragma unroll
    for (int i = 0; i < 8; i++) {
        float2 v0 = unpk(c[i][0]), v1 = unpk(c[i][1]);
        float2 v2 = unpk(c[i][2]), v3 = unpk(c[i][3]);
        float* Cp = C + (long)(bm + tm + i) * N + bn + tn;
        float4 o0 = make_float4(v0.x + bb0.x, v0.y + bb0.y, v1.x + bb0.z, v1.y + bb0.w);
        float4 o1 = make_float4(v2.x + bb1.x, v2.y + bb1.y, v3.x + bb1.z, v3.y + bb1.w);
        *(float4*)Cp       = o0;
        *(float4*)(Cp + 4) = o1;
    }
}

// ---------------- NT GEMM: C[M,N] = A[M,K] @ B[N,K]^T (scores = hs @ emb^T) --------
// N = 50000 (mult of 8, not of 128): row-guard on B loads, 8-col guard on store.
__global__ void __launch_bounds__(256, 2) gemm_nt(
    long a_off, const float* __restrict__ Bm,
    float* __restrict__ C, int M, int N, int K)
{
    const float* A = g_scratch + a_off;

    __shared__ __align__(16) float As[16 * TS];
    __shared__ __align__(16) float Bs[16 * TS];

    const int t = threadIdx.x;
    const int bm = blockIdx.y * 128, bn = blockIdx.x * 128;

    const int warp = t >> 5, lane = t & 31;
    const int tm = (warp >> 1) * 32 + (lane >> 3) * 8;
    const int tn = (warp & 1) * 64 + (lane & 7) * 8;

    const int ar = t >> 1, ak = (t & 1) << 3;     // both A and B fills: row 0..127, k 0/8
    const long nrow = bn + ar;
    const bool bvalid = (nrow < N);

    const float* Ap = A + (long)(bm + ar) * K;
    const float* Bp = Bm + (bvalid ? nrow : 0) * (long)K;

    unsigned long long c[8][4] = {};

    float4 z4 = make_float4(0.f, 0.f, 0.f, 0.f);
    float4 pa0 = *(const float4*)(Ap + ak);
    float4 pa1 = *(const float4*)(Ap + ak + 4);
    float4 pb0 = bvalid ? *(const float4*)(Bp + ak)     : z4;
    float4 pb1 = bvalid ? *(const float4*)(Bp + ak + 4) : z4;

    for (int k0 = 0; k0 < K; k0 += 16) {
        __syncthreads();
        As[(ak + 0) * TS + ar] = pa0.x;
        As[(ak + 1) * TS + ar] = pa0.y;
        As[(ak + 2) * TS + ar] = pa0.z;
        As[(ak + 3) * TS + ar] = pa0.w;
        As[(ak + 4) * TS + ar] = pa1.x;
        As[(ak + 5) * TS + ar] = pa1.y;
        As[(ak + 6) * TS + ar] = pa1.z;
        As[(ak + 7) * TS + ar] = pa1.w;
        Bs[(ak + 0) * TS + ar] = pb0.x;
        Bs[(ak + 1) * TS + ar] = pb0.y;
        Bs[(ak + 2) * TS + ar] = pb0.z;
        Bs[(ak + 3) * TS + ar] = pb0.w;
        Bs[(ak + 4) * TS + ar] = pb1.x;
        Bs[(ak + 5) * TS + ar] = pb1.y;
        Bs[(ak + 6) * TS + ar] = pb1.z;
        Bs[(ak + 7) * TS + ar] = pb1.w;
        __syncthreads();
        if (k0 + 16 < K) {
            pa0 = *(const float4*)(Ap + k0 + 16 + ak);
            pa1 = *(const float4*)(Ap + k0 + 16 + ak + 4);
            pb0 = bvalid ? *(const float4*)(Bp + k0 + 16 + ak)     : z4;
            pb1 = bvalid ? *(const float4*)(Bp + k0 + 16 + ak + 4) : z4;
        }
#pragma unroll
        for (int k = 0; k < 16; k++) {
            const float* as = &As[k * TS + tm];
            float4 a0 = *(const float4*)as;
            float4 a1 = *(const float4*)(as + 4);
            const float* bs = &Bs[k * TS + tn];
            ulonglong2 b0 = *(const ulonglong2*)bs;
            ulonglong2 b1 = *(const ulonglong2*)(bs + 4);
            FMA_ROWS(a0, a1, b0, b1);
        }
    }

    const int n0 = bn + tn;                       // multiple of 8; N % 8 == 0
    if (n0 < N) {
#pragma unroll
        for (int i = 0; i < 8; i++) {
            float2 v0 = unpk(c[i][0]), v1 = unpk(c[i][1]);
            float2 v2 = unpk(c[i][2]), v3 = unpk(c[i][3]);
            float* Cp = C + (long)(bm + tm + i) * N + n0;
            *(float4*)Cp       = make_float4(v0.x, v0.y, v1.x, v1.y);
            *(float4*)(Cp + 4) = make_float4(v2.x, v2.y, v3.x, v3.y);
        }
    }
}

// ---------------- adjacency: a = concat(A_in[b]@hWin[b], A_out[b]@hWout[b]) ---------
__global__ void __launch_bounds__(128) adj_kernel(
    const float* __restrict__ Ain, const float* __restrict__ Aout,
    long hin_off, long hout_off, long out_off)
{
    const float* hin  = g_scratch + hin_off;
    const float* hout = g_scratch + hout_off;
    float* out = g_scratch + out_off;

    const int b = blockIdx.x;
    const int d = threadIdx.x;
    __shared__ float sAi[L * L], sAo[L * L];
    __shared__ float shi[L * D], sho[L * D];
    const float* Aib = Ain + (long)b * L * L;
    const float* Aob = Aout + (long)b * L * L;
    const float* hib = hin + (long)b * L * D;
    const float* hob = hout + (long)b * L * D;
    for (int i = d; i < L * L; i += 128) { sAi[i] = Aib[i]; sAo[i] = Aob[i]; }
    for (int i = d; i < L * D; i += 128) { shi[i] = hib[i]; sho[i] = hob[i]; }
    __syncthreads();
    for (int l = 0; l < L; l++) {
        float si = 0.f, so = 0.f;
#pragma unroll 8
        for (int m = 0; m < L; m++) {
            si += sAi[l * L + m] * shi[m * D + d];
            so += sAo[l * L + m] * sho[m * D + d];
        }
        long o = ((long)b * L + l) * (2 * D);
        out[o + d]     = si;
        out[o + D + d] = so;
    }
}

// ---------------- GRU gates (torch r,z,n order) ----------------
__global__ void __launch_bounds__(256) gru_kernel(
    long gi_off, long gh_off,
    const float* __restrict__ hprev_ext, const int* __restrict__ items,
    const float* __restrict__ emb, long out_off)
{
    const float* gi = g_scratch + gi_off;
    const float* gh = g_scratch + gh_off;
    float* out = g_scratch + out_off;

    long i = (long)blockIdx.x * blockDim.x + threadIdx.x;
    if (i >= (long)ROWS * D) return;
    int row = (int)(i >> 7), d = (int)(i & 127);
    long gb = (long)row * (3 * D);
    float ir = gi[gb + d], iz = gi[gb + D + d], in_ = gi[gb + 2 * D + d];
    float hr = gh[gb + d], hz = gh[gb + D + d], hn  = gh[gb + 2 * D + d];
    float hp = items ? emb[(long)items[row] * D + d] : hprev_ext[i];
    float r = sigf(ir + hr);
    float z = sigf(iz + hz);
    float n = tanhf(in_ + r * hn);
    out[i] = (1.0f - z) * n + z * hp;
}

// ---------------- attention readout ----------------
__global__ void __launch_bounds__(128) readout_kernel(
    long fin_off, long fW2_off,
    const int* __restrict__ seq_len,
    const float* __restrict__ W1, const float* __restrict__ b1,
    const float* __restrict__ wq, const float* __restrict__ bq,
    const float* __restrict__ W3, const float* __restrict__ b3,
    long hs_off)
{
    const float* fin = g_scratch + fin_off;
    const float* fW2 = g_scratch + fW2_off;
    float* hs = g_scratch + hs_off;

    const int b = blockIdx.x;
    const int d = threadIdx.x;
    __shared__ float svn[D];
    __shared__ float sg_sh[D];
    __shared__ float gmat[L * D];
    __shared__ float alpha[L];

    const int sl = seq_len[b];
    const float* finb = fin + (long)b * L * D;
    svn[d] = finb[(long)(sl - 1) * D + d];
    __syncthreads();

    float q = b1[d];
    for (int k = 0; k < D; k++) q += svn[k] * W1[k * D + d];

    const float* fW2b = fW2 + (long)b * L * D;
    for (int l = 0; l < L; l++)
        gmat[l * D + d] = sigf(q + fW2b[l * D + d]);
    __syncthreads();

    int w = d >> 5, lane = d & 31;
    for (int l = w; l < L; l += 4) {
        float p = 0.f;
        for (int kk = lane; kk < D; kk += 32) p += gmat[l * D + kk] * wq[kk];
#pragma unroll
        for (int off = 16; off; off >>= 1) p += __shfl_xor_sync(0xFFFFFFFFu, p, off);
        if (lane == 0) alpha[l] = p + bq[0];
    }
    __syncthreads();

    float sg = 0.f;
    for (int l = 0; l < sl; l++) sg += alpha[l] * finb[(long)l * D + d];
    sg_sh[d] = sg;
    __syncthreads();

    float o = b3[d];
    for (int k = 0; k < D; k++) {
        o += svn[k]   * W3[k * D + d];
        o += sg_sh[k] * W3[(D + k) * D + d];
    }
    hs[(long)b * D + d] = o;
}

// ---------------- launcher: pure kernel launches ----------------
extern "C" void kernel_launch(void* const* d_in, const int* in_sizes, int n_in,
                              void* d_out, int out_size)
{
    const int*   items  = (const int*)d_in[0];
    const float* A_in   = (const float*)d_in[1];
    const float* A_out  = (const float*)d_in[2];
    const float* inter  = (const float*)d_in[3];
    const int*   seqlen = (const int*)d_in[4];
    const float* emb    = (const float*)d_in[5];
    const float* W_in   = (const float*)d_in[6];
    const float* b_in   = (const float*)d_in[7];
    const float* W_out  = (const float*)d_in[8];
    const float* b_out  = (const float*)d_in[9];
    const float* W_a    = (const float*)d_in[10];
    const float* U_h    = (const float*)d_in[11];
    const float* b_gru  = (const float*)d_in[12];
    const float* Wi     = (const float*)d_in[13];
    const float* bi     = (const float*)d_in[14];
    const float* Wh     = (const float*)d_in[15];
    const float* bh     = (const float*)d_in[16];
    const float* W1     = (const float*)d_in[17];
    const float* b1     = (const float*)d_in[18];
    const float* W2     = (const float*)d_in[19];
    const float* b2     = (const float*)d_in[20];
    const float* wq     = (const float*)d_in[21];
    const float* bq     = (const float*)d_in[22];
    const float* W3     = (const float*)d_in[23];
    const float* b3     = (const float*)d_in[24];
    float* scores = (float*)d_out;

    const int MT = ROWS / 128;  // 256 M-tiles

    // 1-2: hWin/hWout = emb[items] @ W_{in,out} + b
    gemm_nn<true><<<dim3(1, MT), 256>>>(emb, 0, items, W_in,  b_in,  OFF_HIN,  ROWS, D, D);
    gemm_nn<true><<<dim3(1, MT), 256>>>(emb, 0, items, W_out, b_out, OFF_HOUT, ROWS, D, D);
    // 3: a = concat(A_in@hWin, A_out@hWout)
    adj_kernel<<<BATCH, 128>>>(A_in, A_out, OFF_HIN, OFF_HOUT, OFF_A);
    // 4-5: GRU1 gate inputs
    gemm_nn<false><<<dim3(3, MT), 256>>>(nullptr, OFF_A, nullptr, W_a, b_gru,   OFF_GI, ROWS, 384, 2 * D);
    gemm_nn<true><<<dim3(3, MT), 256>>>(emb, 0, items, U_h, nullptr, OFF_GH, ROWS, 384, D);
    // 6: intra
    gru_kernel<<<(ROWS * D) / 256, 256>>>(OFF_GI, OFF_GH, nullptr, items, emb, OFF_INTRA);
    // 7-8: GRU2 gate inputs (reuse gi/gh)
    gemm_nn<false><<<dim3(3, MT), 256>>>(nullptr, OFF_INTRA, nullptr, Wi, bi, OFF_GI, ROWS, 384, D);
    gemm_nn<false><<<dim3(3, MT), 256>>>(inter, 0, nullptr, Wh, bh, OFF_GH, ROWS, 384, D);
    // 9: final
    gru_kernel<<<(ROWS * D) / 256, 256>>>(OFF_GI, OFF_GH, inter, nullptr, nullptr, OFF_FINAL);
    // 10: fW2 = final @ W2 + b2
    gemm_nn<false><<<dim3(1, MT), 256>>>(nullptr, OFF_FINAL, nullptr, W2, b2, OFF_FW2, ROWS, D, D);
    // 11: attention readout -> h_s
    readout_kernel<<<BATCH, 128>>>(OFF_FINAL, OFF_FW2, seqlen, W1, b1, wq, bq, W3, b3, OFF_HS);
    // 12: scores = h_s @ emb^T
    gemm_nt<<<dim3((NNODE + 127) / 128, BATCH / 128), 256>>>(OFF_HS, emb, scores, BATCH, NNODE, D);
}

// round 5
// speedup vs baseline: 1.6499x; 1.4906x over previous
#include <cuda_runtime.h>
#include <cuda_bf16.h>
#include <math.h>
#include <cstdint>

#define BATCH 1024
#define L 32
#define D 128
#define NNODE 50000
#define ROWS (BATCH * L)           // 32768
#define RD   (ROWS * D)            // 4194304
#define BD   (BATCH * D)           // 131072
#define ED   (NNODE * D)           // 6400000

// ---------------- float scratch ----------------
#define F_HIN  0L
#define F_HOUT ((long)RD)
#define F_GI   (2L * RD)            // 3RD
#define F_GH   (5L * RD)            // 3RD
#define F_FW2  (8L * RD)
#define F_FIN  (9L * RD)
#define F_TOTAL (10L * RD)
__device__ float g_f[F_TOTAL];

// ---------------- bf16 split scratch (hi plane at off, lo at off + plane size) ----
#define BO_GAH  0L
#define BO_GAL  ((long)RD)
#define BO_AH   (2L * RD)
#define BO_AL   (4L * RD)
#define BO_ITH  (6L * RD)
#define BO_ITL  (7L * RD)
#define BO_FNH  (8L * RD)
#define BO_FNL  (9L * RD)
#define BO_IEH  (10L * RD)
#define BO_IEL  (11L * RD)
#define BO_HSH  (12L * RD)
#define BO_HSL  (12L * RD + BD)
#define BO_EBH  (12L * RD + 2L * BD)
#define BO_EBL  (12L * RD + 2L * BD + ED)
#define BO_WZ   (12L * RD + 2L * BD + 2L * ED)
#define OW_WIN  (BO_WZ)
#define OW_WOUT (OW_WIN  + 2L * 16384)
#define OW_WA   (OW_WOUT + 2L * 16384)
#define OW_UH   (OW_WA   + 2L * 98304)
#define OW_WI   (OW_UH   + 2L * 49152)
#define OW_WH   (OW_WI   + 2L * 49152)
#define OW_W2   (OW_WH   + 2L * 49152)
#define B_TOTAL (OW_W2 + 2L * 16384)
__device__ __nv_bfloat16 g_bf[B_TOTAL];

// ---------------- helpers ----------------
__device__ __forceinline__ void wsplit(float v, __nv_bfloat16* hp, __nv_bfloat16* lp, long i) {
    __nv_bfloat16 h = __float2bfloat16(v);
    hp[i] = h;
    lp[i] = __float2bfloat16(v - __bfloat162float(h));
}
__device__ __forceinline__ float sigf(float x) { return 1.0f / (1.0f + expf(-x)); }

__device__ __forceinline__ void mma_bf16(float* d, const uint32_t* a, const uint32_t* b) {
    asm volatile(
        "mma.sync.aligned.m16n8k16.row.col.f32.bf16.bf16.f32 "
        "{%0,%1,%2,%3}, {%4,%5,%6,%7}, {%8,%9}, {%0,%1,%2,%3};"
        : "+f"(d[0]), "+f"(d[1]), "+f"(d[2]), "+f"(d[3])
        : "r"(a[0]), "r"(a[1]), "r"(a[2]), "r"(a[3]), "r"(b[0]), "r"(b[1]));
}

// ================= split-bf16 tensor-core GEMM (mma.sync HMMA) =================
// C[M,N] = (Ah+Al)[M,K] @ (Bh+Bl)[N,K]^T (+bias), fp32 accum.
// Block tile 128x64, 8 warps (4m x 2n), warp tile 32x32 (2 m-frags x 4 n-frags).
// K-chunk 32. SMEM row stride 40 bf16 (20 words) -> conflict-free frag loads.
#define AST 40
__global__ void __launch_bounds__(256) gemm_mma(
    long ah, long al, long bh, long bl,
    const float* __restrict__ bias,
    float* __restrict__ C_ext, long c_off,
    int N, int K)
{
    const __nv_bfloat16* Ah = g_bf + ah;
    const __nv_bfloat16* Al = g_bf + al;
    const __nv_bfloat16* Bh = g_bf + bh;
    const __nv_bfloat16* Bl = g_bf + bl;
    float* C = C_ext ? C_ext : (g_f + c_off);

    __shared__ __align__(16) __nv_bfloat16 sAh[128 * AST];
    __shared__ __align__(16) __nv_bfloat16 sAl[128 * AST];
    __shared__ __align__(16) __nv_bfloat16 sBh[64 * AST];
    __shared__ __align__(16) __nv_bfloat16 sBl[64 * AST];
    const uint32_t* wAh = (const uint32_t*)sAh;
    const uint32_t* wAl = (const uint32_t*)sAl;
    const uint32_t* wBh = (const uint32_t*)sBh;
    const uint32_t* wBl = (const uint32_t*)sBl;

    const int tid = threadIdx.x;
    const int warp = tid >> 5, lane = tid & 31;
    const int wm = warp >> 1, wn = warp & 1;          // 4m x 2n
    const int g = lane >> 2, tig = lane & 3;

    const long bm = (long)blockIdx.x * 128;
    const int  bn = blockIdx.y * 64;
    const int  nsize = min(64, N - bn);

    // fill indices: A rows via 2 passes of 64, B rows one pass of 64
    const int fr = tid >> 2, fq = tid & 3;            // row 0..63, 16B segment 0..3

    float acc[2][4][4];
#pragma unroll
    for (int i = 0; i < 2; i++)
#pragma unroll
        for (int j = 0; j < 4; j++)
#pragma unroll
            for (int v = 0; v < 4; v++) acc[i][j][v] = 0.f;

    const uint4 z4 = make_uint4(0, 0, 0, 0);
    const int nch = K >> 5;
    for (int c = 0; c < nch; c++) {
        const int k0 = c << 5;
        if (c) __syncthreads();
        // A planes: 128 rows x 32 cols
#pragma unroll
        for (int p = 0; p < 2; p++) {
            const int r = fr + p * 64;
            const long go = (bm + r) * (long)K + k0 + fq * 8;
            *(uint4*)&sAh[r * AST + fq * 8] = *(const uint4*)(Ah + go);
            *(uint4*)&sAl[r * AST + fq * 8] = *(const uint4*)(Al + go);
        }
        // B planes: 64 rows x 32 cols (guard rows >= nsize)
        {
            const int r = fr;
            if (r < nsize) {
                const long go = (bn + r) * (long)K + k0 + fq * 8;
                *(uint4*)&sBh[r * AST + fq * 8] = *(const uint4*)(Bh + go);
                *(uint4*)&sBl[r * AST + fq * 8] = *(const uint4*)(Bl + go);
            } else {
                *(uint4*)&sBh[r * AST + fq * 8] = z4;
                *(uint4*)&sBl[r * AST + fq * 8] = z4;
            }
        }
        __syncthreads();

#pragma unroll
        for (int ks = 0; ks < 2; ks++) {
            const int cw = ks * 8 + tig;
            uint32_t ahf[2][4], alf[2][4], bhf[4][2], blf[4][2];
#pragma unroll
            for (int mf = 0; mf < 2; mf++) {
                const int rA = wm * 32 + mf * 16 + g;
                ahf[mf][0] = wAh[rA * 20 + cw];
                ahf[mf][1] = wAh[(rA + 8) * 20 + cw];
                ahf[mf][2] = wAh[rA * 20 + cw + 4];
                ahf[mf][3] = wAh[(rA + 8) * 20 + cw + 4];
                alf[mf][0] = wAl[rA * 20 + cw];
                alf[mf][1] = wAl[(rA + 8) * 20 + cw];
                alf[mf][2] = wAl[rA * 20 + cw + 4];
                alf[mf][3] = wAl[(rA + 8) * 20 + cw + 4];
            }
#pragma unroll
            for (int nf = 0; nf < 4; nf++) {
                const int rB = wn * 32 + nf * 8 + g;
                bhf[nf][0] = wBh[rB * 20 + cw];
                bhf[nf][1] = wBh[rB * 20 + cw + 4];
                blf[nf][0] = wBl[rB * 20 + cw];
                blf[nf][1] = wBl[rB * 20 + cw + 4];
            }
#pragma unroll
            for (int mf = 0; mf < 2; mf++)
#pragma unroll
                for (int nf = 0; nf < 4; nf++) {
                    mma_bf16(acc[mf][nf], ahf[mf], bhf[nf]);
                    mma_bf16(acc[mf][nf], ahf[mf], blf[nf]);
                    mma_bf16(acc[mf][nf], alf[mf], bhf[nf]);
                }
        }
    }

    // epilogue
#pragma unroll
    for (int mf = 0; mf < 2; mf++) {
        const long row = bm + wm * 32 + mf * 16 + g;
#pragma unroll
        for (int nf = 0; nf < 4; nf++) {
            const int col = bn + wn * 32 + nf * 8 + tig * 2;
            if (col < N) {
                float bx = bias ? bias[col] : 0.f;
                float by = bias ? bias[col + 1] : 0.f;
                *(float2*)&C[row * N + col] =
                    make_float2(acc[mf][nf][0] + bx, acc[mf][nf][1] + by);
                *(float2*)&C[(row + 8) * N + col] =
                    make_float2(acc[mf][nf][2] + bx, acc[mf][nf][3] + by);
            }
        }
    }
}

// ================= prep / elementwise kernels =================

// transpose-convert weight W[K,N] -> planes [N,K]
__global__ void __launch_bounds__(256) wprep(const float* __restrict__ W, long hoff, int K, int N) {
    long i = (long)blockIdx.x * 256 + threadIdx.x;
    if (i >= (long)K * N) return;
    int n = (int)(i / K), k = (int)(i - (long)n * K);
    wsplit(W[(long)k * N + n], g_bf + hoff, g_bf + hoff + (long)N * K, i);
}

// straight convert src[n] -> planes
__global__ void __launch_bounds__(256) conv_split(const float* __restrict__ src, long hoff, long n) {
    long i = (long)blockIdx.x * 256 + threadIdx.x;
    if (i >= n) return;
    wsplit(src[i], g_bf + hoff, g_bf + hoff + n, i);
}

// gathered emb rows -> planes [ROWS,128]
__global__ void __launch_bounds__(256) gather_conv(const int* __restrict__ items, const float* __restrict__ emb) {
    long i = (long)blockIdx.x * 256 + threadIdx.x;
    if (i >= (long)RD) return;
    int row = (int)(i >> 7), d = (int)(i & 127);
    wsplit(emb[(long)items[row] * D + d], g_bf + BO_GAH, g_bf + BO_GAL, i);
}

// adjacency: a = concat(A_in[b]@hin[b], A_out[b]@hout[b]) -> split planes [ROWS,256]
__global__ void __launch_bounds__(128) adj_kernel(const float* __restrict__ Ain, const float* __restrict__ Aout) {
    const float* hin  = g_f + F_HIN;
    const float* hout = g_f + F_HOUT;
    const int b = blockIdx.x, d = threadIdx.x;
    __shared__ float sAi[L * L], sAo[L * L], shi[L * D], sho[L * D];
    const float* Aib = Ain + (long)b * L * L;
    const float* Aob = Aout + (long)b * L * L;
    const float* hib = hin + (long)b * L * D;
    const float* hob = hout + (long)b * L * D;
    for (int i = d; i < L * L; i += 128) { sAi[i] = Aib[i]; sAo[i] = Aob[i]; }
    for (int i = d; i < L * D; i += 128) { shi[i] = hib[i]; sho[i] = hob[i]; }
    __syncthreads();
    for (int l = 0; l < L; l++) {
        float si = 0.f, so = 0.f;
#pragma unroll 8
        for (int m = 0; m < L; m++) {
            si += sAi[l * L + m] * shi[m * D + d];
            so += sAo[l * L + m] * sho[m * D + d];
        }
        long o = ((long)b * L + l) * 256;
        wsplit(si, g_bf + BO_AH, g_bf + BO_AL, o + d);
        wsplit(so, g_bf + BO_AH, g_bf + BO_AL, o + 128 + d);
    }
}

// GRU1: h_prev = emb[items]; out -> intra split planes
__global__ void __launch_bounds__(256) gru1_kernel(const int* __restrict__ items, const float* __restrict__ emb) {
    long i = (long)blockIdx.x * 256 + threadIdx.x;
    if (i >= (long)RD) return;
    int row = (int)(i >> 7), d = (int)(i & 127);
    long gb = (long)row * 384;
    const float* gi = g_f + F_GI;
    const float* gh = g_f + F_GH;
    float r = sigf(gi[gb + d] + gh[gb + d]);
    float z = sigf(gi[gb + 128 + d] + gh[gb + 128 + d]);
    float n = tanhf(gi[gb + 256 + d] + r * gh[gb + 256 + d]);
    float hp = emb[(long)items[row] * D + d];
    wsplit((1.f - z) * n + z * hp, g_bf + BO_ITH, g_bf + BO_ITL, i);
}

// GRU2: h_prev = inter; out -> final fp32 + split planes
__global__ void __launch_bounds__(256) gru2_kernel(const float* __restrict__ inter) {
    long i = (long)blockIdx.x * 256 + threadIdx.x;
    if (i >= (long)RD) return;
    int row = (int)(i >> 7), d = (int)(i & 127);
    long gb = (long)row * 384;
    const float* gi = g_f + F_GI;
    const float* gh = g_f + F_GH;
    float r = sigf(gi[gb + d] + gh[gb + d]);
    float z = sigf(gi[gb + 128 + d] + gh[gb + 128 + d]);
    float n = tanhf(gi[gb + 256 + d] + r * gh[gb + 256 + d]);
    float v = (1.f - z) * n + z * inter[i];
    g_f[F_FIN + i] = v;
    wsplit(v, g_bf + BO_FNH, g_bf + BO_FNL, i);
}

// attention readout -> hs split planes
__global__ void __launch_bounds__(128) readout_kernel(
    const int* __restrict__ seq_len,
    const float* __restrict__ W1, const float* __restrict__ b1,
    const float* __restrict__ wq, const float* __restrict__ bq,
    const float* __restrict__ W3, const float* __restrict__ b3)
{
    const float* fin = g_f + F_FIN;
    const float* fW2 = g_f + F_FW2;
    const int b = blockIdx.x, d = threadIdx.x;
    __shared__ float svn[D], sg_sh[D], gmat[L * D], alpha[L];

    const int sl = seq_len[b];
    const float* finb = fin + (long)b * L * D;
    svn[d] = finb[(long)(sl - 1) * D + d];
    __syncthreads();

    float q = b1[d];
    for (int k = 0; k < D; k++) q += svn[k] * W1[k * D + d];

    const float* fW2b = fW2 + (long)b * L * D;
    for (int l = 0; l < L; l++)
        gmat[l * D + d] = sigf(q + fW2b[l * D + d]);
    __syncthreads();

    int w = d >> 5, lane = d & 31;
    for (int l = w; l < L; l += 4) {
        float p = 0.f;
        for (int kk = lane; kk < D; kk += 32) p += gmat[l * D + kk] * wq[kk];
#pragma unroll
        for (int off = 16; off; off >>= 1) p += __shfl_xor_sync(0xFFFFFFFFu, p, off);
        if (lane == 0) alpha[l] = p + bq[0];
    }
    __syncthreads();

    float sg = 0.f;
    for (int l = 0; l < sl; l++) sg += alpha[l] * finb[(long)l * D + d];
    sg_sh[d] = sg;
    __syncthreads();

    float o = b3[d];
    for (int k = 0; k < D; k++) {
        o += svn[k]   * W3[k * D + d];
        o += sg_sh[k] * W3[(D + k) * D + d];
    }
    wsplit(o, g_bf + BO_HSH, g_bf + BO_HSL, (long)b * D + d);
}

// ================= launcher: pure kernel launches =================
extern "C" void kernel_launch(void* const* d_in, const int* in_sizes, int n_in,
                              void* d_out, int out_size)
{
    const int*   items  = (const int*)d_in[0];
    const float* A_in   = (const float*)d_in[1];
    const float* A_out  = (const float*)d_in[2];
    const float* inter  = (const float*)d_in[3];
    const int*   seqlen = (const int*)d_in[4];
    const float* emb    = (const float*)d_in[5];
    const float* W_in   = (const float*)d_in[6];
    const float* b_in   = (const float*)d_in[7];
    const float* W_out  = (const float*)d_in[8];
    const float* b_out  = (const float*)d_in[9];
    const float* W_a    = (const float*)d_in[10];
    const float* U_h    = (const float*)d_in[11];
    const float* b_gru  = (const float*)d_in[12];
    const float* Wi     = (const float*)d_in[13];
    const float* bi     = (const float*)d_in[14];
    const float* Wh     = (const float*)d_in[15];
    const float* bh     = (const float*)d_in[16];
    const float* W1     = (const float*)d_in[17];
    const float* b1     = (const float*)d_in[18];
    const float* W2     = (const float*)d_in[19];
    const float* b2     = (const float*)d_in[20];
    const float* wq     = (const float*)d_in[21];
    const float* bq     = (const float*)d_in[22];
    const float* W3     = (const float*)d_in[23];
    const float* b3     = (const float*)d_in[24];
    float* scores = (float*)d_out;

    const int MT = ROWS / 128;   // 256 M-tiles

    // --- weight / input conversions ---
    wprep<<<(128 * 128 + 255) / 256, 256>>>(W_in,  OW_WIN,  128, 128);
    wprep<<<(128 * 128 + 255) / 256, 256>>>(W_out, OW_WOUT, 128, 128);
    wprep<<<(256 * 384 + 255) / 256, 256>>>(W_a,   OW_WA,   256, 384);
    wprep<<<(128 * 384 + 255) / 256, 256>>>(U_h,   OW_UH,   128, 384);
    wprep<<<(128 * 384 + 255) / 256, 256>>>(Wi,    OW_WI,   128, 384);
    wprep<<<(128 * 384 + 255) / 256, 256>>>(Wh,    OW_WH,   128, 384);
    wprep<<<(128 * 128 + 255) / 256, 256>>>(W2,    OW_W2,   128, 128);
    conv_split<<<((long)ED + 255) / 256, 256>>>(emb,   BO_EBH, ED);
    conv_split<<<((long)RD + 255) / 256, 256>>>(inter, BO_IEH, RD);
    gather_conv<<<(RD + 255) / 256, 256>>>(items, emb);

    // --- GGNN ---
    gemm_mma<<<dim3(MT, 2), 256>>>(BO_GAH, BO_GAL, OW_WIN,  OW_WIN  + 16384, b_in,  nullptr, F_HIN,  128, 128);
    gemm_mma<<<dim3(MT, 2), 256>>>(BO_GAH, BO_GAL, OW_WOUT, OW_WOUT + 16384, b_out, nullptr, F_HOUT, 128, 128);
    adj_kernel<<<BATCH, 128>>>(A_in, A_out);
    gemm_mma<<<dim3(MT, 6), 256>>>(BO_AH,  BO_AL,  OW_WA,   OW_WA   + 98304, b_gru,   nullptr, F_GI, 384, 256);
    gemm_mma<<<dim3(MT, 6), 256>>>(BO_GAH, BO_GAL, OW_UH,   OW_UH   + 49152, nullptr, nullptr, F_GH, 384, 128);
    gru1_kernel<<<(RD + 255) / 256, 256>>>(items, emb);
    // --- ItemFusing ---
    gemm_mma<<<dim3(MT, 6), 256>>>(BO_ITH, BO_ITL, OW_WI,   OW_WI   + 49152, bi, nullptr, F_GI, 384, 128);
    gemm_mma<<<dim3(MT, 6), 256>>>(BO_IEH, BO_IEL, OW_WH,   OW_WH   + 49152, bh, nullptr, F_GH, 384, 128);
    gru2_kernel<<<(RD + 255) / 256, 256>>>(inter);
    // --- readout ---
    gemm_mma<<<dim3(MT, 2), 256>>>(BO_FNH, BO_FNL, OW_W2,   OW_W2   + 16384, b2, nullptr, F_FW2, 128, 128);
    readout_kernel<<<BATCH, 128>>>(seqlen, W1, b1, wq, bq, W3, b3);
    // --- scores = hs @ emb^T ---
    gemm_mma<<<dim3(BATCH / 128, (NNODE + 63) / 64), 256>>>(
        BO_HSH, BO_HSL, BO_EBH, BO_EBL, nullptr, scores, 0, NNODE, 128);
}

// round 6
// speedup vs baseline: 1.7874x; 1.0834x over previous
#include <cuda_runtime.h>
#include <cuda_bf16.h>
#include <math.h>
#include <cstdint>

#define BATCH 1024
#define L 32
#define D 128
#define NNODE 50000
#define ROWS (BATCH * L)           // 32768
#define RD   (ROWS * D)            // 4194304
#define BD   (BATCH * D)           // 131072
#define ED   (NNODE * D)           // 6400000

// ---------------- float scratch ----------------
#define F_HIO  0L                   // [ROWS, 256] = hin | hout interleaved
#define F_GI   (2L * RD)            // 3RD
#define F_GH   (5L * RD)            // 3RD
#define F_FW2  (8L * RD)
#define F_FIN  (9L * RD)
#define F_TOTAL (10L * RD)
__device__ float g_f[F_TOTAL];
__device__ float g_bio[256];        // concat(b_in, b_out)

// ---------------- bf16 split planes (hi at off, lo at off + plane size) ----------
#define BO_GAH  0L
#define BO_GAL  ((long)RD)
#define BO_AH   (2L * RD)
#define BO_AL   (4L * RD)
#define BO_ITH  (6L * RD)
#define BO_ITL  (7L * RD)
#define BO_FNH  (8L * RD)
#define BO_FNL  (9L * RD)
#define BO_IEH  (10L * RD)
#define BO_IEL  (11L * RD)
#define BO_HSH  (12L * RD)
#define BO_HSL  (12L * RD + BD)
#define BO_EBH  (12L * RD + 2L * BD)
#define BO_EBL  (12L * RD + 2L * BD + ED)
#define BO_WZ   (12L * RD + 2L * BD + 2L * ED)
#define OW_WIO  (BO_WZ)             // [256,128] -> hi 32768 + lo 32768
#define OW_WA   (OW_WIO + 65536L)   // [384,256]
#define OW_UH   (OW_WA + 196608L)   // [384,128]
#define OW_WI   (OW_UH + 98304L)
#define OW_WH   (OW_WI + 98304L)
#define OW_W2   (OW_WH + 98304L)    // [128,128]
#define B_TOTAL (OW_W2 + 32768L)
__device__ __nv_bfloat16 g_bf[B_TOTAL];

// ---------------- helpers ----------------
__device__ __forceinline__ uint32_t smem_u32(const void* p) {
    uint32_t a;
    asm("{ .reg .u64 t; cvta.to.shared.u64 t, %1; cvt.u32.u64 %0, t; }" : "=r"(a) : "l"(p));
    return a;
}
__device__ __forceinline__ void wsplit(float v, __nv_bfloat16* hp, __nv_bfloat16* lp, long i) {
    __nv_bfloat16 h = __float2bfloat16(v);
    hp[i] = h;
    lp[i] = __float2bfloat16(v - __bfloat162float(h));
}
__device__ __forceinline__ float sigf(float x) { return 1.0f / (1.0f + expf(-x)); }

__device__ __forceinline__ void mma_bf16(float* d, const uint32_t* a, const uint32_t* b) {
    asm volatile(
        "mma.sync.aligned.m16n8k16.row.col.f32.bf16.bf16.f32 "
        "{%0,%1,%2,%3}, {%4,%5,%6,%7}, {%8,%9}, {%0,%1,%2,%3};"
        : "+f"(d[0]), "+f"(d[1]), "+f"(d[2]), "+f"(d[3])
        : "r"(a[0]), "r"(a[1]), "r"(a[2]), "r"(a[3]), "r"(b[0]), "r"(b[1]));
}

// ================= split-bf16 tensor-core GEMM, cp.async double-buffered =========
// C[M,N] = (Ah+Al)[M,K] @ (Bh+Bl)[N,K]^T (+bias), fp32 accum.
// Block 128x128, 8 warps (2m x 4n), warp tile 64x32 (4 mf x 4 nf). K-chunk 32.
// SMEM row stride 40 bf16 -> conflict-free 32b frag loads (banks 20g+tig all distinct).
#define BM 128
#define BN 128
#define BK 32
#define PLANE (128 * 40)            // bf16 elements per plane buffer (10240B)
#define STAGE (4 * PLANE)           // Ah, Al, Bh, Bl
#define GEMM_SMEM (2 * STAGE * 2)   // 2 stages, bytes = 81920

__global__ void __launch_bounds__(256) gemm_mma(
    long ah, long al, long bh, long bl,
    const float* __restrict__ bias_ext, int bias_mode,
    float* __restrict__ C_ext, long c_off, int N, int K)
{
    extern __shared__ __align__(16) __nv_bfloat16 dsm[];
    const __nv_bfloat16* Ah = g_bf + ah;
    const __nv_bfloat16* Al = g_bf + al;
    const __nv_bfloat16* Bh = g_bf + bh;
    const __nv_bfloat16* Bl = g_bf + bl;
    float* C = C_ext ? C_ext : (g_f + c_off);
    const float* bias = (bias_mode == 1) ? bias_ext : (bias_mode == 2 ? g_bio : nullptr);

    const int tid = threadIdx.x;
    const int warp = tid >> 5, lane = tid & 31;
    const int wm = warp & 1, wn = warp >> 1;          // 2m x 4n
    const int g = lane >> 2, tig = lane & 3;

    const long bm = (long)blockIdx.x * BM;
    const int bn = blockIdx.y * BN;
    const int nsize = min(BN, N - bn);

    // fill coords: row fr (0..127), 32B segment fc (cols fc..fc+15)
    const int fr = tid >> 1;
    const int fc = (tid & 1) * 16;
    const long arow = bm + fr;
    const long brow = bn + (fr < nsize ? fr : 0);
    const int bok = (fr < nsize) ? 16 : 0;
    const uint32_t smb = smem_u32(dsm);
    const uint32_t doff = (uint32_t)(fr * 80 + fc * 2); // bytes within plane

    float acc[4][4][4];
#pragma unroll
    for (int i = 0; i < 4; i++)
#pragma unroll
        for (int j = 0; j < 4; j++)
#pragma unroll
            for (int v = 0; v < 4; v++) acc[i][j][v] = 0.f;

#define LOADCH(c_, st_) do {                                                           \
    const long k0_ = (long)(c_) * BK;                                                  \
    const uint32_t b_ = smb + (uint32_t)(st_) * (STAGE * 2);                           \
    const __nv_bfloat16* pa_ = Ah + arow * K + k0_ + fc;                               \
    const __nv_bfloat16* qa_ = Al + arow * K + k0_ + fc;                               \
    const __nv_bfloat16* pb_ = Bh + brow * K + k0_ + fc;                               \
    const __nv_bfloat16* qb_ = Bl + brow * K + k0_ + fc;                               \
    asm volatile("cp.async.cg.shared.global [%0], [%1], 16;" :: "r"(b_ + doff), "l"(pa_)); \
    asm volatile("cp.async.cg.shared.global [%0], [%1], 16;" :: "r"(b_ + doff + 16), "l"(pa_ + 8)); \
    asm volatile("cp.async.cg.shared.global [%0], [%1], 16;" :: "r"(b_ + PLANE * 2 + doff), "l"(qa_)); \
    asm volatile("cp.async.cg.shared.global [%0], [%1], 16;" :: "r"(b_ + PLANE * 2 + doff + 16), "l"(qa_ + 8)); \
    asm volatile("cp.async.cg.shared.global [%0], [%1], 16, %2;" :: "r"(b_ + 2 * PLANE * 2 + doff), "l"(pb_), "r"(bok)); \
    asm volatile("cp.async.cg.shared.global [%0], [%1], 16, %2;" :: "r"(b_ + 2 * PLANE * 2 + doff + 16), "l"(pb_ + 8), "r"(bok)); \
    asm volatile("cp.async.cg.shared.global [%0], [%1], 16, %2;" :: "r"(b_ + 3 * PLANE * 2 + doff), "l"(qb_), "r"(bok)); \
    asm volatile("cp.async.cg.shared.global [%0], [%1], 16, %2;" :: "r"(b_ + 3 * PLANE * 2 + doff + 16), "l"(qb_ + 8), "r"(bok)); \
    asm volatile("cp.async.commit_group;");                                            \
} while (0)

    const int nch = K / BK;
    LOADCH(0, 0);
    for (int c = 0; c < nch; c++) {
        const int st = c & 1;
        if (c + 1 < nch) {
            LOADCH(c + 1, st ^ 1);
            asm volatile("cp.async.wait_group 1;");
        } else {
            asm volatile("cp.async.wait_group 0;");
        }
        __syncthreads();

        const uint32_t* wAh = (const uint32_t*)(dsm + st * STAGE);
        const uint32_t* wAl = wAh + PLANE / 2;
        const uint32_t* wBh = wAl + PLANE / 2;
        const uint32_t* wBl = wBh + PLANE / 2;

#pragma unroll
        for (int ks = 0; ks < 2; ks++) {
            const int cw = ks * 8 + tig;
            uint32_t ahf[4][4], alf[4][4], bhf[4][2], blf[4][2];
#pragma unroll
            for (int mf = 0; mf < 4; mf++) {
                const int rA = wm * 64 + mf * 16 + g;
                ahf[mf][0] = wAh[rA * 20 + cw];
                ahf[mf][1] = wAh[(rA + 8) * 20 + cw];
                ahf[mf][2] = wAh[rA * 20 + cw + 4];
                ahf[mf][3] = wAh[(rA + 8) * 20 + cw + 4];
                alf[mf][0] = wAl[rA * 20 + cw];
                alf[mf][1] = wAl[(rA + 8) * 20 + cw];
                alf[mf][2] = wAl[rA * 20 + cw + 4];
                alf[mf][3] = wAl[(rA + 8) * 20 + cw + 4];
            }
#pragma unroll
            for (int nf = 0; nf < 4; nf++) {
                const int rB = wn * 32 + nf * 8 + g;
                bhf[nf][0] = wBh[rB * 20 + cw];
                bhf[nf][1] = wBh[rB * 20 + cw + 4];
                blf[nf][0] = wBl[rB * 20 + cw];
                blf[nf][1] = wBl[rB * 20 + cw + 4];
            }
#pragma unroll
            for (int mf = 0; mf < 4; mf++)
#pragma unroll
                for (int nf = 0; nf < 4; nf++) {
                    mma_bf16(acc[mf][nf], ahf[mf], bhf[nf]);
                    mma_bf16(acc[mf][nf], ahf[mf], blf[nf]);
                    mma_bf16(acc[mf][nf], alf[mf], bhf[nf]);
                }
        }
        __syncthreads();
    }

    // epilogue
#pragma unroll
    for (int mf = 0; mf < 4; mf++) {
        const long row = bm + wm * 64 + mf * 16 + g;
#pragma unroll
        for (int nf = 0; nf < 4; nf++) {
            const int col = bn + wn * 32 + nf * 8 + tig * 2;
            if (col < N) {
                float bx = bias ? bias[col] : 0.f;
                float by = bias ? bias[col + 1] : 0.f;
                *(float2*)&C[row * N + col] =
                    make_float2(acc[mf][nf][0] + bx, acc[mf][nf][1] + by);
                *(float2*)&C[(row + 8) * N + col] =
                    make_float2(acc[mf][nf][2] + bx, acc[mf][nf][3] + by);
            }
        }
    }
#undef LOADCH
}

// ================= fused prep: all weight transposes + conversions + gather =======
// index ranges (in order): Wio 32768 | bio 256 | Wa 98304 | Uh 49152 | Wi 49152 |
//                          Wh 49152 | W2 16384 | emb ED | inter RD | gather RD
#define PREP_TOTAL (32768L + 256 + 98304 + 3 * 49152 + 16384 + (long)ED + 2L * RD)
__global__ void __launch_bounds__(256) prep_all(
    const float* __restrict__ W_in, const float* __restrict__ b_in,
    const float* __restrict__ W_out, const float* __restrict__ b_out,
    const float* __restrict__ W_a, const float* __restrict__ U_h,
    const float* __restrict__ Wi, const float* __restrict__ Wh,
    const float* __restrict__ W2,
    const float* __restrict__ emb, const float* __restrict__ inter,
    const int* __restrict__ items)
{
    long i = (long)blockIdx.x * 256 + threadIdx.x;
    if (i < 32768) {                                    // W_io [256,128]
        int n = (int)(i >> 7), k = (int)(i & 127);
        float v = (n < 128) ? W_in[k * 128 + n] : W_out[k * 128 + (n - 128)];
        wsplit(v, g_bf + OW_WIO, g_bf + OW_WIO + 32768, i);
        return;
    }
    i -= 32768;
    if (i < 256) { g_bio[i] = (i < 128) ? b_in[i] : b_out[i - 128]; return; }
    i -= 256;
    if (i < 98304) {                                    // W_a [384,256]
        int n = (int)(i >> 8), k = (int)(i & 255);
        wsplit(W_a[(long)k * 384 + n], g_bf + OW_WA, g_bf + OW_WA + 98304, i);
        return;
    }
    i -= 98304;
    if (i < 49152) {                                    // U_h [384,128]
        int n = (int)(i >> 7), k = (int)(i & 127);
        wsplit(U_h[(long)k * 384 + n], g_bf + OW_UH, g_bf + OW_UH + 49152, i);
        return;
    }
    i -= 49152;
    if (i < 49152) {                                    // Wi [384,128]
        int n = (int)(i >> 7), k = (int)(i & 127);
        wsplit(Wi[(long)k * 384 + n], g_bf + OW_WI, g_bf + OW_WI + 49152, i);
        return;
    }
    i -= 49152;
    if (i < 49152) {                                    // Wh [384,128]
        int n = (int)(i >> 7), k = (int)(i & 127);
        wsplit(Wh[(long)k * 384 + n], g_bf + OW_WH, g_bf + OW_WH + 49152, i);
        return;
    }
    i -= 49152;
    if (i < 16384) {                                    // W2 [128,128]
        int n = (int)(i >> 7), k = (int)(i & 127);
        wsplit(W2[(long)k * 128 + n], g_bf + OW_W2, g_bf + OW_W2 + 16384, i);
        return;
    }
    i -= 16384;
    if (i < (long)ED) {                                 // emb conversion
        wsplit(emb[i], g_bf + BO_EBH, g_bf + BO_EBH + (long)ED, i);
        return;
    }
    i -= (long)ED;
    if (i < (long)RD) {                                 // inter conversion
        wsplit(inter[i], g_bf + BO_IEH, g_bf + BO_IEH + (long)RD, i);
        return;
    }
    i -= (long)RD;
    if (i < (long)RD) {                                 // gather emb[items]
        int row = (int)(i >> 7), d = (int)(i & 127);
        wsplit(emb[(long)items[row] * D + d], g_bf + BO_GAH, g_bf + BO_GAL, i);
    }
}

// ================= adjacency: a = concat(A_in[b]@hin[b], A_out[b]@hout[b]) ========
__global__ void __launch_bounds__(128) adj_kernel(const float* __restrict__ Ain, const float* __restrict__ Aout) {
    const float* hio = g_f + F_HIO;                     // [ROWS, 256]: hin | hout
    const int b = blockIdx.x, d = threadIdx.x;
    __shared__ float sAi[L * L], sAo[L * L], shi[L * D], sho[L * D];
    const float* Aib = Ain + (long)b * L * L;
    const float* Aob = Aout + (long)b * L * L;
    for (int i = d; i < L * L; i += 128) { sAi[i] = Aib[i]; sAo[i] = Aob[i]; }
    for (int i = d; i < L * D; i += 128) {
        int m = i >> 7, dd = i & 127;
        long r = ((long)b * L + m) * 256;
        shi[i] = hio[r + dd];
        sho[i] = hio[r + 128 + dd];
    }
    __syncthreads();
    for (int l = 0; l < L; l++) {
        float si = 0.f, so = 0.f;
#pragma unroll 8
        for (int m = 0; m < L; m++) {
            si += sAi[l * L + m] * shi[m * D + d];
            so += sAo[l * L + m] * sho[m * D + d];
        }
        long o = ((long)b * L + l) * 256;
        wsplit(si, g_bf + BO_AH, g_bf + BO_AL, o + d);
        wsplit(so, g_bf + BO_AH, g_bf + BO_AL, o + 128 + d);
    }
}

// ================= GRU kernels =================
__global__ void __launch_bounds__(256) gru1_kernel(const int* __restrict__ items, const float* __restrict__ emb) {
    long i = (long)blockIdx.x * 256 + threadIdx.x;
    if (i >= (long)RD) return;
    int row = (int)(i >> 7), d = (int)(i & 127);
    long gb = (long)row * 384;
    const float* gi = g_f + F_GI;
    const float* gh = g_f + F_GH;
    float r = sigf(gi[gb + d] + gh[gb + d]);
    float z = sigf(gi[gb + 128 + d] + gh[gb + 128 + d]);
    float n = tanhf(gi[gb + 256 + d] + r * gh[gb + 256 + d]);
    float hp = emb[(long)items[row] * D + d];
    wsplit((1.f - z) * n + z * hp, g_bf + BO_ITH, g_bf + BO_ITL, i);
}

__global__ void __launch_bounds__(256) gru2_kernel(const float* __restrict__ inter) {
    long i = (long)blockIdx.x * 256 + threadIdx.x;
    if (i >= (long)RD) return;
    int row = (int)(i >> 7), d = (int)(i & 127);
    long gb = (long)row * 384;
    const float* gi = g_f + F_GI;
    const float* gh = g_f + F_GH;
    float r = sigf(gi[gb + d] + gh[gb + d]);
    float z = sigf(gi[gb + 128 + d] + gh[gb + 128 + d]);
    float n = tanhf(gi[gb + 256 + d] + r * gh[gb + 256 + d]);
    float v = (1.f - z) * n + z * inter[i];
    g_f[F_FIN + i] = v;
    wsplit(v, g_bf + BO_FNH, g_bf + BO_FNL, i);
}

// ================= attention readout -> hs planes =================
__global__ void __launch_bounds__(128) readout_kernel(
    const int* __restrict__ seq_len,
    const float* __restrict__ W1, const float* __restrict__ b1,
    const float* __restrict__ wq, const float* __restrict__ bq,
    const float* __restrict__ W3, const float* __restrict__ b3)
{
    const float* fin = g_f + F_FIN;
    const float* fW2 = g_f + F_FW2;
    const int b = blockIdx.x, d = threadIdx.x;
    __shared__ float svn[D], sg_sh[D], gmat[L * D], alpha[L];

    const int sl = seq_len[b];
    const float* finb = fin + (long)b * L * D;
    svn[d] = finb[(long)(sl - 1) * D + d];
    __syncthreads();

    float q = b1[d];
    for (int k = 0; k < D; k++) q += svn[k] * W1[k * D + d];

    const float* fW2b = fW2 + (long)b * L * D;
    for (int l = 0; l < L; l++)
        gmat[l * D + d] = sigf(q + fW2b[l * D + d]);
    __syncthreads();

    int w = d >> 5, lane = d & 31;
    for (int l = w; l < L; l += 4) {
        float p = 0.f;
        for (int kk = lane; kk < D; kk += 32) p += gmat[l * D + kk] * wq[kk];
#pragma unroll
        for (int off = 16; off; off >>= 1) p += __shfl_xor_sync(0xFFFFFFFFu, p, off);
        if (lane == 0) alpha[l] = p + bq[0];
    }
    __syncthreads();

    float sg = 0.f;
    for (int l = 0; l < sl; l++) sg += alpha[l] * finb[(long)l * D + d];
    sg_sh[d] = sg;
    __syncthreads();

    float o = b3[d];
    for (int k = 0; k < D; k++) {
        o += svn[k]   * W3[k * D + d];
        o += sg_sh[k] * W3[(D + k) * D + d];
    }
    wsplit(o, g_bf + BO_HSH, g_bf + BO_HSL, (long)b * D + d);
}

// ================= launcher =================
extern "C" void kernel_launch(void* const* d_in, const int* in_sizes, int n_in,
                              void* d_out, int out_size)
{
    const int*   items  = (const int*)d_in[0];
    const float* A_in   = (const float*)d_in[1];
    const float* A_out  = (const float*)d_in[2];
    const float* inter  = (const float*)d_in[3];
    const int*   seqlen = (const int*)d_in[4];
    const float* emb    = (const float*)d_in[5];
    const float* W_in   = (const float*)d_in[6];
    const float* b_in   = (const float*)d_in[7];
    const float* W_out  = (const float*)d_in[8];
    const float* b_out  = (const float*)d_in[9];
    const float* W_a    = (const float*)d_in[10];
    const float* U_h    = (const float*)d_in[11];
    const float* b_gru  = (const float*)d_in[12];
    const float* Wi     = (const float*)d_in[13];
    const float* bi     = (const float*)d_in[14];
    const float* Wh     = (const float*)d_in[15];
    const float* bh     = (const float*)d_in[16];
    const float* W1     = (const float*)d_in[17];
    const float* b1     = (const float*)d_in[18];
    const float* W2     = (const float*)d_in[19];
    const float* b2     = (const float*)d_in[20];
    const float* wq     = (const float*)d_in[21];
    const float* bq     = (const float*)d_in[22];
    const float* W3     = (const float*)d_in[23];
    const float* b3     = (const float*)d_in[24];
    float* scores = (float*)d_out;

    cudaFuncSetAttribute(gemm_mma, cudaFuncAttributeMaxDynamicSharedMemorySize, GEMM_SMEM);

    const int MT = ROWS / 128;   // 256 M-tiles

    prep_all<<<(int)(PREP_TOTAL / 256), 256>>>(W_in, b_in, W_out, b_out, W_a, U_h,
                                               Wi, Wh, W2, emb, inter, items);
    // hio = gathered @ [W_in|W_out] + [b_in|b_out]   (N=256, K=128)
    gemm_mma<<<dim3(MT, 2), 256, GEMM_SMEM>>>(BO_GAH, BO_GAL, OW_WIO, OW_WIO + 32768,
                                              nullptr, 2, nullptr, F_HIO, 256, 128);
    adj_kernel<<<BATCH, 128>>>(A_in, A_out);
    gemm_mma<<<dim3(MT, 3), 256, GEMM_SMEM>>>(BO_AH, BO_AL, OW_WA, OW_WA + 98304,
                                              b_gru, 1, nullptr, F_GI, 384, 256);
    gemm_mma<<<dim3(MT, 3), 256, GEMM_SMEM>>>(BO_GAH, BO_GAL, OW_UH, OW_UH + 49152,
                                              nullptr, 0, nullptr, F_GH, 384, 128);
    gru1_kernel<<<(RD + 255) / 256, 256>>>(items, emb);
    gemm_mma<<<dim3(MT, 3), 256, GEMM_SMEM>>>(BO_ITH, BO_ITL, OW_WI, OW_WI + 49152,
                                              bi, 1, nullptr, F_GI, 384, 128);
    gemm_mma<<<dim3(MT, 3), 256, GEMM_SMEM>>>(BO_IEH, BO_IEL, OW_WH, OW_WH + 49152,
                                              bh, 1, nullptr, F_GH, 384, 128);
    gru2_kernel<<<(RD + 255) / 256, 256>>>(inter);
    gemm_mma<<<dim3(MT, 1), 256, GEMM_SMEM>>>(BO_FNH, BO_FNL, OW_W2, OW_W2 + 16384,
                                              b2, 1, nullptr, F_FW2, 128, 128);
    readout_kernel<<<BATCH, 128>>>(seqlen, W1, b1, wq, bq, W3, b3);
    gemm_mma<<<dim3(BATCH / 128, (NNODE + 127) / 128), 256, GEMM_SMEM>>>(
        BO_HSH, BO_HSL, BO_EBH, BO_EBL, nullptr, 0, scores, 0, NNODE, 128);
}

// round 7
// speedup vs baseline: 1.8672x; 1.0446x over previous
#include <cuda_runtime.h>
#include <cuda_bf16.h>
#include <math.h>
#include <cstdint>

#define BATCH 1024
#define L 32
#define D 128
#define NNODE 50000
#define ROWS (BATCH * L)           // 32768
#define RD   (ROWS * D)            // 4194304
#define BD   (BATCH * D)           // 131072
#define ED   (NNODE * D)           // 6400000

// ---------------- float scratch ----------------
#define F_HIO  0L                   // [ROWS, 256] = hin | hout
#define F_GI   (2L * RD)            // 3RD
#define F_GH   (5L * RD)            // 3RD
#define F_FW2  (8L * RD)
#define F_FIN  (9L * RD)
#define F_TOTAL (10L * RD)
__device__ float g_f[F_TOTAL];
__device__ float g_bio[256];        // concat(b_in, b_out)

// ---------------- bf16 split planes (hi at off, lo at off + plane size) ----------
#define BO_GAH  0L
#define BO_GAL  ((long)RD)
#define BO_AH   (2L * RD)
#define BO_AL   (4L * RD)
#define BO_ITH  (6L * RD)
#define BO_ITL  (7L * RD)
#define BO_FNH  (8L * RD)
#define BO_FNL  (9L * RD)
#define BO_IEH  (10L * RD)
#define BO_IEL  (11L * RD)
#define BO_HSH  (12L * RD)
#define BO_HSL  (12L * RD + BD)
#define BO_EBH  (12L * RD + 2L * BD)
#define BO_EBL  (12L * RD + 2L * BD + ED)
#define BO_WZ   (12L * RD + 2L * BD + 2L * ED)
#define OW_WIO  (BO_WZ)             // [256,128]
#define OW_WA   (OW_WIO + 65536L)   // [384,256]
#define OW_UH   (OW_WA + 196608L)   // [384,128]
#define OW_WI   (OW_UH + 98304L)
#define OW_WH   (OW_WI + 98304L)
#define OW_W2   (OW_WH + 98304L)    // [128,128]
#define B_TOTAL (OW_W2 + 32768L)
__device__ __nv_bfloat16 g_bf[B_TOTAL];

// ---------------- helpers ----------------
__device__ __forceinline__ uint32_t smem_u32(const void* p) {
    uint32_t a;
    asm("{ .reg .u64 t; cvta.to.shared.u64 t, %1; cvt.u32.u64 %0, t; }" : "=r"(a) : "l"(p));
    return a;
}
__device__ __forceinline__ void wsplit(float v, __nv_bfloat16* hp, __nv_bfloat16* lp, long i) {
    __nv_bfloat16 h = __float2bfloat16(v);
    hp[i] = h;
    lp[i] = __float2bfloat16(v - __bfloat162float(h));
}
__device__ __forceinline__ float sigf(float x) { return 1.0f / (1.0f + expf(-x)); }

__device__ __forceinline__ void mma_bf16(float* d, const uint32_t* a, const uint32_t* b) {
    asm volatile(
        "mma.sync.aligned.m16n8k16.row.col.f32.bf16.bf16.f32 "
        "{%0,%1,%2,%3}, {%4,%5,%6,%7}, {%8,%9}, {%0,%1,%2,%3};"
        : "+f"(d[0]), "+f"(d[1]), "+f"(d[2]), "+f"(d[3])
        : "r"(a[0]), "r"(a[1]), "r"(a[2]), "r"(a[3]), "r"(b[0]), "r"(b[1]));
}
__device__ __forceinline__ void ldsm4(uint32_t* r, uint32_t a) {
    asm volatile("ldmatrix.sync.aligned.m8n8.x4.shared.b16 {%0,%1,%2,%3}, [%4];"
        : "=r"(r[0]), "=r"(r[1]), "=r"(r[2]), "=r"(r[3]) : "r"(a));
}

// ================= split-bf16 tensor-core GEMM, cp.async + ldmatrix ==============
// C[M,N] = (Ah+Al)[M,K] @ (Bh+Bl)[N,K]^T (+bias), fp32 accum.
// Block 128x128, 8 warps (2m x 4n), warp tile 64x32. K-chunk 32.
// SMEM row stride 40 bf16 (80B) -> LDSM phases conflict-free.
#define BM 128
#define BN 128
#define BK 32
#define PLANE (128 * 40)            // bf16 elems per plane (10240B)
#define PLANEB (PLANE * 2)          // bytes
#define STAGEB (4 * PLANEB)         // Ah, Al, Bh, Bl (bytes)
#define GEMM_SMEM (2 * STAGEB)      // 81920

__global__ void __launch_bounds__(256) gemm_mma(
    long ah, long al, long bh, long bl,
    const float* __restrict__ bias_ext, int bias_mode,
    float* __restrict__ C_ext, long c_off, int N, int K)
{
    extern __shared__ __align__(16) __nv_bfloat16 dsm[];
    const __nv_bfloat16* Ah = g_bf + ah;
    const __nv_bfloat16* Al = g_bf + al;
    const __nv_bfloat16* Bh = g_bf + bh;
    const __nv_bfloat16* Bl = g_bf + bl;
    float* C = C_ext ? C_ext : (g_f + c_off);
    const float* bias = (bias_mode == 1) ? bias_ext : (bias_mode == 2 ? g_bio : nullptr);

    const int tid = threadIdx.x;
    const int warp = tid >> 5, lane = tid & 31;
    const int wm = warp & 1, wn = warp >> 1;          // 2m x 4n
    const int g = lane >> 2, tig = lane & 3;

    const long bm = (long)blockIdx.x * BM;
    const int bn = blockIdx.y * BN;
    const int nsize = min(BN, N - bn);

    // fill coords
    const int fr = tid >> 1;
    const int fc = (tid & 1) * 16;
    const long arow = bm + fr;
    const long brow = bn + (fr < nsize ? fr : 0);
    const int bok = (fr < nsize) ? 16 : 0;
    const uint32_t smb = smem_u32(dsm);
    const uint32_t doff = (uint32_t)(fr * 80 + fc * 2);

    // ldmatrix lane offsets (bytes within a plane)
    const uint32_t laneA = (uint32_t)(((lane & 7) + (((lane >> 3) & 1) << 3)) * 80 + (lane >> 4) * 16);
    const uint32_t laneB = (uint32_t)(((lane & 7) + ((lane >> 4) << 3)) * 80 + ((lane >> 3) & 1) * 16);
    const uint32_t aBaseA = (uint32_t)(wm * 64 * 80) + laneA;     // + mf*16*80 + ks*32
    const uint32_t aBaseB = (uint32_t)(wn * 32 * 80) + laneB;     // + np*16*80 + ks*32

    float acc[4][4][4];
#pragma unroll
    for (int i = 0; i < 4; i++)
#pragma unroll
        for (int j = 0; j < 4; j++)
#pragma unroll
            for (int v = 0; v < 4; v++) acc[i][j][v] = 0.f;

#define LOADCH(c_, st_) do {                                                           \
    const long k0_ = (long)(c_) * BK;                                                  \
    const uint32_t b_ = smb + (uint32_t)(st_) * STAGEB;                                \
    const __nv_bfloat16* pa_ = Ah + arow * K + k0_ + fc;                               \
    const __nv_bfloat16* qa_ = Al + arow * K + k0_ + fc;                               \
    const __nv_bfloat16* pb_ = Bh + brow * K + k0_ + fc;                               \
    const __nv_bfloat16* qb_ = Bl + brow * K + k0_ + fc;                               \
    asm volatile("cp.async.cg.shared.global [%0], [%1], 16;" :: "r"(b_ + doff), "l"(pa_)); \
    asm volatile("cp.async.cg.shared.global [%0], [%1], 16;" :: "r"(b_ + doff + 16), "l"(pa_ + 8)); \
    asm volatile("cp.async.cg.shared.global [%0], [%1], 16;" :: "r"(b_ + PLANEB + doff), "l"(qa_)); \
    asm volatile("cp.async.cg.shared.global [%0], [%1], 16;" :: "r"(b_ + PLANEB + doff + 16), "l"(qa_ + 8)); \
    asm volatile("cp.async.cg.shared.global [%0], [%1], 16, %2;" :: "r"(b_ + 2 * PLANEB + doff), "l"(pb_), "r"(bok)); \
    asm volatile("cp.async.cg.shared.global [%0], [%1], 16, %2;" :: "r"(b_ + 2 * PLANEB + doff + 16), "l"(pb_ + 8), "r"(bok)); \
    asm volatile("cp.async.cg.shared.global [%0], [%1], 16, %2;" :: "r"(b_ + 3 * PLANEB + doff), "l"(qb_), "r"(bok)); \
    asm volatile("cp.async.cg.shared.global [%0], [%1], 16, %2;" :: "r"(b_ + 3 * PLANEB + doff + 16), "l"(qb_ + 8), "r"(bok)); \
    asm volatile("cp.async.commit_group;");                                            \
} while (0)

    const int nch = K / BK;
    LOADCH(0, 0);
    for (int c = 0; c < nch; c++) {
        const int st = c & 1;
        if (c + 1 < nch) {
            LOADCH(c + 1, st ^ 1);
            asm volatile("cp.async.wait_group 1;");
        } else {
            asm volatile("cp.async.wait_group 0;");
        }
        __syncthreads();

        const uint32_t stb = smb + (uint32_t)st * STAGEB;
        const uint32_t pAh = stb + aBaseA;
        const uint32_t pAl = stb + PLANEB + aBaseA;
        const uint32_t pBh = stb + 2 * PLANEB + aBaseB;
        const uint32_t pBl = stb + 3 * PLANEB + aBaseB;

#pragma unroll
        for (int ks = 0; ks < 2; ks++) {
            const uint32_t ko = (uint32_t)(ks * 32);
            uint32_t ahf[4][4], alf[4][4], bhf[4][2], blf[4][2];
#pragma unroll
            for (int mf = 0; mf < 4; mf++) {
                ldsm4(ahf[mf], pAh + (uint32_t)(mf * 16 * 80) + ko);
                ldsm4(alf[mf], pAl + (uint32_t)(mf * 16 * 80) + ko);
            }
#pragma unroll
            for (int np = 0; np < 2; np++) {
                uint32_t bt[4];
                ldsm4(bt, pBh + (uint32_t)(np * 16 * 80) + ko);
                bhf[np * 2][0] = bt[0]; bhf[np * 2][1] = bt[1];
                bhf[np * 2 + 1][0] = bt[2]; bhf[np * 2 + 1][1] = bt[3];
                ldsm4(bt, pBl + (uint32_t)(np * 16 * 80) + ko);
                blf[np * 2][0] = bt[0]; blf[np * 2][1] = bt[1];
                blf[np * 2 + 1][0] = bt[2]; blf[np * 2 + 1][1] = bt[3];
            }
#pragma unroll
            for (int mf = 0; mf < 4; mf++)
#pragma unroll
                for (int nf = 0; nf < 4; nf++) {
                    mma_bf16(acc[mf][nf], ahf[mf], bhf[nf]);
                    mma_bf16(acc[mf][nf], ahf[mf], blf[nf]);
                    mma_bf16(acc[mf][nf], alf[mf], bhf[nf]);
                }
        }
        __syncthreads();
    }

    // epilogue
#pragma unroll
    for (int mf = 0; mf < 4; mf++) {
        const long row = bm + wm * 64 + mf * 16 + g;
#pragma unroll
        for (int nf = 0; nf < 4; nf++) {
            const int col = bn + wn * 32 + nf * 8 + tig * 2;
            if (col < N) {
                float bx = bias ? bias[col] : 0.f;
                float by = bias ? bias[col + 1] : 0.f;
                *(float2*)&C[row * N + col] =
                    make_float2(acc[mf][nf][0] + bx, acc[mf][nf][1] + by);
                *(float2*)&C[(row + 8) * N + col] =
                    make_float2(acc[mf][nf][2] + bx, acc[mf][nf][3] + by);
            }
        }
    }
#undef LOADCH
}

// ================= fused prep =================
#define PREP_TOTAL (32768L + 256 + 98304 + 3 * 49152 + 16384 + (long)ED + 2L * RD)
__global__ void __launch_bounds__(256) prep_all(
    const float* __restrict__ W_in, const float* __restrict__ b_in,
    const float* __restrict__ W_out, const float* __restrict__ b_out,
    const float* __restrict__ W_a, const float* __restrict__ U_h,
    const float* __restrict__ Wi, const float* __restrict__ Wh,
    const float* __restrict__ W2,
    const float* __restrict__ emb, const float* __restrict__ inter,
    const int* __restrict__ items)
{
    long i = (long)blockIdx.x * 256 + threadIdx.x;
    if (i < 32768) {
        int n = (int)(i >> 7), k = (int)(i & 127);
        float v = (n < 128) ? W_in[k * 128 + n] : W_out[k * 128 + (n - 128)];
        wsplit(v, g_bf + OW_WIO, g_bf + OW_WIO + 32768, i);
        return;
    }
    i -= 32768;
    if (i < 256) { g_bio[i] = (i < 128) ? b_in[i] : b_out[i - 128]; return; }
    i -= 256;
    if (i < 98304) {
        int n = (int)(i >> 8), k = (int)(i & 255);
        wsplit(W_a[(long)k * 384 + n], g_bf + OW_WA, g_bf + OW_WA + 98304, i);
        return;
    }
    i -= 98304;
    if (i < 49152) {
        int n = (int)(i >> 7), k = (int)(i & 127);
        wsplit(U_h[(long)k * 384 + n], g_bf + OW_UH, g_bf + OW_UH + 49152, i);
        return;
    }
    i -= 49152;
    if (i < 49152) {
        int n = (int)(i >> 7), k = (int)(i & 127);
        wsplit(Wi[(long)k * 384 + n], g_bf + OW_WI, g_bf + OW_WI + 49152, i);
        return;
    }
    i -= 49152;
    if (i < 49152) {
        int n = (int)(i >> 7), k = (int)(i & 127);
        wsplit(Wh[(long)k * 384 + n], g_bf + OW_WH, g_bf + OW_WH + 49152, i);
        return;
    }
    i -= 49152;
    if (i < 16384) {
        int n = (int)(i >> 7), k = (int)(i & 127);
        wsplit(W2[(long)k * 128 + n], g_bf + OW_W2, g_bf + OW_W2 + 16384, i);
        return;
    }
    i -= 16384;
    if (i < (long)ED) {
        wsplit(emb[i], g_bf + BO_EBH, g_bf + BO_EBH + (long)ED, i);
        return;
    }
    i -= (long)ED;
    if (i < (long)RD) {
        wsplit(inter[i], g_bf + BO_IEH, g_bf + BO_IEH + (long)RD, i);
        return;
    }
    i -= (long)RD;
    if (i < (long)RD) {
        int row = (int)(i >> 7), d = (int)(i & 127);
        wsplit(emb[(long)items[row] * D + d], g_bf + BO_GAH, g_bf + BO_GAL, i);
    }
}

// ================= adjacency =================
__global__ void __launch_bounds__(128) adj_kernel(const float* __restrict__ Ain, const float* __restrict__ Aout) {
    const float* hio = g_f + F_HIO;
    const int b = blockIdx.x, d = threadIdx.x;
    __shared__ float sAi[L * L], sAo[L * L], shi[L * D], sho[L * D];
    const float* Aib = Ain + (long)b * L * L;
    const float* Aob = Aout + (long)b * L * L;
    for (int i = d; i < L * L; i += 128) { sAi[i] = Aib[i]; sAo[i] = Aob[i]; }
    for (int i = d; i < L * D; i += 128) {
        int m = i >> 7, dd = i & 127;
        long r = ((long)b * L + m) * 256;
        shi[i] = hio[r + dd];
        sho[i] = hio[r + 128 + dd];
    }
    __syncthreads();
    for (int l = 0; l < L; l++) {
        float si = 0.f, so = 0.f;
#pragma unroll 8
        for (int m = 0; m < L; m++) {
            si += sAi[l * L + m] * shi[m * D + d];
            so += sAo[l * L + m] * sho[m * D + d];
        }
        long o = ((long)b * L + l) * 256;
        wsplit(si, g_bf + BO_AH, g_bf + BO_AL, o + d);
        wsplit(so, g_bf + BO_AH, g_bf + BO_AL, o + 128 + d);
    }
}

// ================= GRU kernels =================
__global__ void __launch_bounds__(256) gru1_kernel(const int* __restrict__ items, const float* __restrict__ emb) {
    long i = (long)blockIdx.x * 256 + threadIdx.x;
    if (i >= (long)RD) return;
    int row = (int)(i >> 7), d = (int)(i & 127);
    long gb = (long)row * 384;
    const float* gi = g_f + F_GI;
    const float* gh = g_f + F_GH;
    float r = sigf(gi[gb + d] + gh[gb + d]);
    float z = sigf(gi[gb + 128 + d] + gh[gb + 128 + d]);
    float n = tanhf(gi[gb + 256 + d] + r * gh[gb + 256 + d]);
    float hp = emb[(long)items[row] * D + d];
    wsplit((1.f - z) * n + z * hp, g_bf + BO_ITH, g_bf + BO_ITL, i);
}

__global__ void __launch_bounds__(256) gru2_kernel(const float* __restrict__ inter) {
    long i = (long)blockIdx.x * 256 + threadIdx.x;
    if (i >= (long)RD) return;
    int row = (int)(i >> 7), d = (int)(i & 127);
    long gb = (long)row * 384;
    const float* gi = g_f + F_GI;
    const float* gh = g_f + F_GH;
    float r = sigf(gi[gb + d] + gh[gb + d]);
    float z = sigf(gi[gb + 128 + d] + gh[gb + 128 + d]);
    float n = tanhf(gi[gb + 256 + d] + r * gh[gb + 256 + d]);
    float v = (1.f - z) * n + z * inter[i];
    g_f[F_FIN + i] = v;
    wsplit(v, g_bf + BO_FNH, g_bf + BO_FNL, i);
}

// ================= attention readout =================
__global__ void __launch_bounds__(128) readout_kernel(
    const int* __restrict__ seq_len,
    const float* __restrict__ W1, const float* __restrict__ b1,
    const float* __restrict__ wq, const float* __restrict__ bq,
    const float* __restrict__ W3, const float* __restrict__ b3)
{
    const float* fin = g_f + F_FIN;
    const float* fW2 = g_f + F_FW2;
    const int b = blockIdx.x, d = threadIdx.x;
    __shared__ float svn[D], sg_sh[D], gmat[L * D], alpha[L];

    const int sl = seq_len[b];
    const float* finb = fin + (long)b * L * D;
    svn[d] = finb[(long)(sl - 1) * D + d];
    __syncthreads();

    float q = b1[d];
    for (int k = 0; k < D; k++) q += svn[k] * W1[k * D + d];

    const float* fW2b = fW2 + (long)b * L * D;
    for (int l = 0; l < L; l++)
        gmat[l * D + d] = sigf(q + fW2b[l * D + d]);
    __syncthreads();

    int w = d >> 5, lane = d & 31;
    for (int l = w; l < L; l += 4) {
        float p = 0.f;
        for (int kk = lane; kk < D; kk += 32) p += gmat[l * D + kk] * wq[kk];
#pragma unroll
        for (int off = 16; off; off >>= 1) p += __shfl_xor_sync(0xFFFFFFFFu, p, off);
        if (lane == 0) alpha[l] = p + bq[0];
    }
    __syncthreads();

    float sg = 0.f;
    for (int l = 0; l < sl; l++) sg += alpha[l] * finb[(long)l * D + d];
    sg_sh[d] = sg;
    __syncthreads();

    float o = b3[d];
    for (int k = 0; k < D; k++) {
        o += svn[k]   * W3[k * D + d];
        o += sg_sh[k] * W3[(D + k) * D + d];
    }
    wsplit(o, g_bf + BO_HSH, g_bf + BO_HSL, (long)b * D + d);
}

// ================= launcher =================
extern "C" void kernel_launch(void* const* d_in, const int* in_sizes, int n_in,
                              void* d_out, int out_size)
{
    const int*   items  = (const int*)d_in[0];
    const float* A_in   = (const float*)d_in[1];
    const float* A_out  = (const float*)d_in[2];
    const float* inter  = (const float*)d_in[3];
    const int*   seqlen = (const int*)d_in[4];
    const float* emb    = (const float*)d_in[5];
    const float* W_in   = (const float*)d_in[6];
    const float* b_in   = (const float*)d_in[7];
    const float* W_out  = (const float*)d_in[8];
    const float* b_out  = (const float*)d_in[9];
    const float* W_a    = (const float*)d_in[10];
    const float* U_h    = (const float*)d_in[11];
    const float* b_gru  = (const float*)d_in[12];
    const float* Wi     = (const float*)d_in[13];
    const float* bi     = (const float*)d_in[14];
    const float* Wh     = (const float*)d_in[15];
    const float* bh     = (const float*)d_in[16];
    const float* W1     = (const float*)d_in[17];
    const float* b1     = (const float*)d_in[18];
    const float* W2     = (const float*)d_in[19];
    const float* b2     = (const float*)d_in[20];
    const float* wq     = (const float*)d_in[21];
    const float* bq     = (const float*)d_in[22];
    const float* W3     = (const float*)d_in[23];
    const float* b3     = (const float*)d_in[24];
    float* scores = (float*)d_out;

    cudaFuncSetAttribute(gemm_mma, cudaFuncAttributeMaxDynamicSharedMemorySize, GEMM_SMEM);

    const int MT = ROWS / 128;   // 256 M-tiles

    prep_all<<<(int)(PREP_TOTAL / 256), 256>>>(W_in, b_in, W_out, b_out, W_a, U_h,
                                               Wi, Wh, W2, emb, inter, items);
    gemm_mma<<<dim3(MT, 2), 256, GEMM_SMEM>>>(BO_GAH, BO_GAL, OW_WIO, OW_WIO + 32768,
                                              nullptr, 2, nullptr, F_HIO, 256, 128);
    adj_kernel<<<BATCH, 128>>>(A_in, A_out);
    gemm_mma<<<dim3(MT, 3), 256, GEMM_SMEM>>>(BO_AH, BO_AL, OW_WA, OW_WA + 98304,
                                              b_gru, 1, nullptr, F_GI, 384, 256);
    gemm_mma<<<dim3(MT, 3), 256, GEMM_SMEM>>>(BO_GAH, BO_GAL, OW_UH, OW_UH + 49152,
                                              nullptr, 0, nullptr, F_GH, 384, 128);
    gru1_kernel<<<(RD + 255) / 256, 256>>>(items, emb);
    gemm_mma<<<dim3(MT, 3), 256, GEMM_SMEM>>>(BO_ITH, BO_ITL, OW_WI, OW_WI + 49152,
                                              bi, 1, nullptr, F_GI, 384, 128);
    gemm_mma<<<dim3(MT, 3), 256, GEMM_SMEM>>>(BO_IEH, BO_IEL, OW_WH, OW_WH + 49152,
                                              bh, 1, nullptr, F_GH, 384, 128);
    gru2_kernel<<<(RD + 255) / 256, 256>>>(inter);
    gemm_mma<<<dim3(MT, 1), 256, GEMM_SMEM>>>(BO_FNH, BO_FNL, OW_W2, OW_W2 + 16384,
                                              b2, 1, nullptr, F_FW2, 128, 128);
    readout_kernel<<<BATCH, 128>>>(seqlen, W1, b1, wq, bq, W3, b3);
    gemm_mma<<<dim3(BATCH / 128, (NNODE + 127) / 128), 256, GEMM_SMEM>>>(
        BO_HSH, BO_HSL, BO_EBH, BO_EBL, nullptr, 0, scores, 0, NNODE, 128);
}